// round 10
// baseline (speedup 1.0000x reference)
#include <cuda_runtime.h>
#include <math.h>
#include <cstdint>

#define MAXN   50000
#define MAXE   10000
#define MAXNNZ 600000

// ---------------- scratch (static __device__, no allocations) ----------------
__device__ float g_ax[MAXN * 4];
__device__ float g_ae[MAXE * 4];
__device__ float g_A1[128 * 4];
__device__ float g_A2[128 * 4];
__device__ float g_alpha[MAXNNZ * 4];
__device__ float g_xbar[MAXE * 512];   // per-edge, per-head weighted sums of x rows [E][4][128]
__device__ float g_eh[MAXE * 256];     // xbar @ W1 (per head)
__device__ float g_h[MAXN * 256];      // elu(conv1 out)
__device__ float g_xh2[MAXN * 64];     // h @ W2
__device__ float g_eh2[MAXE * 64];
__device__ int g_cntN[MAXN], g_cntE[MAXE];
__device__ int g_curN[MAXN], g_curE[MAXE];
__device__ int g_offN[MAXN], g_offE[MAXE];
__device__ int g_csrN[MAXNNZ], g_csrE[MAXNNZ];
__device__ int g_totN, g_totE;

// ---------------- CSR construction ----------------
__global__ void zero_counts_kernel(int N, int E) {
    int i = blockIdx.x * blockDim.x + threadIdx.x;
    int s = gridDim.x * blockDim.x;
    if (i == 0) { g_totN = 0; g_totE = 0; }
    for (int j = i; j < N; j += s) { g_cntN[j] = 0; g_curN[j] = 0; }
    for (int j = i; j < E; j += s) { g_cntE[j] = 0; g_curE[j] = 0; }
}

__global__ void count_kernel(const int* __restrict__ node, const int* __restrict__ hedge, int nnz) {
    int t = blockIdx.x * blockDim.x + threadIdx.x;
    int stride4 = gridDim.x * blockDim.x * 4;
    for (int j0 = t * 4; j0 < nnz; j0 += stride4) {
        if (j0 + 3 < nnz) {
            int4 n4 = *(const int4*)&node[j0];
            int4 h4 = *(const int4*)&hedge[j0];
            atomicAdd(&g_cntN[n4.x], 1); atomicAdd(&g_cntN[n4.y], 1);
            atomicAdd(&g_cntN[n4.z], 1); atomicAdd(&g_cntN[n4.w], 1);
            atomicAdd(&g_cntE[h4.x], 1); atomicAdd(&g_cntE[h4.y], 1);
            atomicAdd(&g_cntE[h4.z], 1); atomicAdd(&g_cntE[h4.w], 1);
        } else {
            for (int j = j0; j < nnz; j++) {
                atomicAdd(&g_cntN[node[j]], 1);
                atomicAdd(&g_cntE[hedge[j]], 1);
            }
        }
    }
}

__device__ __forceinline__ void alloc_ranges(const int* __restrict__ cnt, int* __restrict__ off,
                                             int* total, int n, int gwarp, int nwarps, int lane) {
    for (int j0 = gwarp * 32; j0 < n; j0 += nwarps * 32) {
        int j = j0 + lane;
        int c = (j < n) ? cnt[j] : 0;
        int x = c;
        #pragma unroll
        for (int o = 1; o < 32; o <<= 1) {
            int y = __shfl_up_sync(0xffffffffu, x, o);
            if (lane >= o) x += y;
        }
        int wtot = __shfl_sync(0xffffffffu, x, 31);
        int base = 0;
        if (lane == 0) base = atomicAdd(total, wtot);
        base = __shfl_sync(0xffffffffu, base, 0);
        if (j < n) off[j] = base + x - c;
    }
}

__global__ void alloc_kernel(int N, int E) {
    int t = blockIdx.x * blockDim.x + threadIdx.x;
    int gwarp = t >> 5, lane = t & 31;
    int nwarps = (gridDim.x * blockDim.x) >> 5;
    alloc_ranges(g_cntN, g_offN, &g_totN, N, gwarp, nwarps, lane);
    alloc_ranges(g_cntE, g_offE, &g_totE, E, gwarp, nwarps, lane);
}

__global__ void scatter_kernel(const int* __restrict__ node, const int* __restrict__ hedge, int nnz) {
    int t = blockIdx.x * blockDim.x + threadIdx.x;
    int stride4 = gridDim.x * blockDim.x * 4;
    for (int j0 = t * 4; j0 < nnz; j0 += stride4) {
        if (j0 + 3 < nnz) {
            int4 n4 = *(const int4*)&node[j0];
            int4 h4 = *(const int4*)&hedge[j0];
            g_csrN[g_offN[n4.x] + atomicAdd(&g_curN[n4.x], 1)] = j0 + 0;
            g_csrN[g_offN[n4.y] + atomicAdd(&g_curN[n4.y], 1)] = j0 + 1;
            g_csrN[g_offN[n4.z] + atomicAdd(&g_curN[n4.z], 1)] = j0 + 2;
            g_csrN[g_offN[n4.w] + atomicAdd(&g_curN[n4.w], 1)] = j0 + 3;
            g_csrE[g_offE[h4.x] + atomicAdd(&g_curE[h4.x], 1)] = j0 + 0;
            g_csrE[g_offE[h4.y] + atomicAdd(&g_curE[h4.y], 1)] = j0 + 1;
            g_csrE[g_offE[h4.z] + atomicAdd(&g_curE[h4.z], 1)] = j0 + 2;
            g_csrE[g_offE[h4.w] + atomicAdd(&g_curE[h4.w], 1)] = j0 + 3;
        } else {
            for (int j = j0; j < nnz; j++) {
                int n = node[j], h = hedge[j];
                g_csrN[g_offN[n] + atomicAdd(&g_curN[n], 1)] = j;
                g_csrE[g_offE[h] + atomicAdd(&g_curE[h], 1)] = j;
            }
        }
    }
}

// ---------------- tiled fp32 GEMM (round-5 version, used for conv2) ----------------
template <int BM, int BN, int BK, int TM, int TN>
__global__ __launch_bounds__(256) void sgemm_kernel(const float* __restrict__ A,
                                                    const float* __restrict__ B,
                                                    float* __restrict__ C, int M, int N, int K) {
    constexpr int THREADS = (BM / TM) * (BN / TN);
    __shared__ float As[BK][BM];
    __shared__ float Bs[BK][BN];
    int tid = threadIdx.x;
    int tx = tid % (BN / TN);
    int ty = tid / (BN / TN);
    int rowBase = blockIdx.x * BM;
    int colBase = blockIdx.y * BN;
    float acc[TM][TN] = {};
    for (int kt = 0; kt < K; kt += BK) {
        #pragma unroll
        for (int l = tid; l < BM * BK / 4; l += THREADS) {
            int r = l / (BK / 4), c4 = l % (BK / 4);
            int gr = rowBase + r;
            float4 v = make_float4(0.f, 0.f, 0.f, 0.f);
            if (gr < M) v = *(const float4*)&A[(size_t)gr * K + kt + c4 * 4];
            As[c4 * 4 + 0][r] = v.x;
            As[c4 * 4 + 1][r] = v.y;
            As[c4 * 4 + 2][r] = v.z;
            As[c4 * 4 + 3][r] = v.w;
        }
        #pragma unroll
        for (int l = tid; l < BK * BN / 4; l += THREADS) {
            int r = l / (BN / 4), c4 = l % (BN / 4);
            *(float4*)&Bs[r][c4 * 4] = *(const float4*)&B[(size_t)(kt + r) * N + colBase + c4 * 4];
        }
        __syncthreads();
        #pragma unroll
        for (int k = 0; k < BK; k++) {
            float ar[TM], br[TN];
            #pragma unroll
            for (int i = 0; i < TM; i++) ar[i] = As[k][ty * TM + i];
            #pragma unroll
            for (int j = 0; j < TN; j++) br[j] = Bs[k][tx * TN + j];
            #pragma unroll
            for (int i = 0; i < TM; i++)
                #pragma unroll
                for (int j = 0; j < TN; j++) acc[i][j] += ar[i] * br[j];
        }
        __syncthreads();
    }
    #pragma unroll
    for (int i = 0; i < TM; i++) {
        int gr = rowBase + ty * TM + i;
        if (gr < M) {
            #pragma unroll
            for (int j4 = 0; j4 < TN / 4; j4++) {
                float4 v = make_float4(acc[i][j4 * 4 + 0], acc[i][j4 * 4 + 1],
                                       acc[i][j4 * 4 + 2], acc[i][j4 * 4 + 3]);
                *(float4*)&C[(size_t)gr * N + colBase + tx * TN + j4 * 4] = v;
            }
        }
    }
}

// ---------------- gemm_eh: eh[e, h*64+j] = sum_k xbar[e][h][k] * W1[k][h*64+j] ----------------
// grid (ceil(E/64), 4 heads); 256 thr; BM=64, BN=64, BK=16, TM=TN=4.
__global__ __launch_bounds__(256) void gemm_eh_kernel(const float* __restrict__ W1, int E) {
    __shared__ float As[16][64];
    __shared__ float Bs[16][64];
    int tid = threadIdx.x;
    int h = blockIdx.y;
    int rowBase = blockIdx.x * 64;
    int tx = tid & 15, ty = tid >> 4;
    float acc[4][4] = {};
    int ar_ = tid >> 2, ac4 = (tid & 3) * 4;     // A tile: 64 rows x 16 cols, 1 float4/thread
    int br_ = tid >> 4, bc4 = (tid & 15) * 4;    // B tile: 16 rows x 64 cols, 1 float4/thread
    for (int kt = 0; kt < 128; kt += 16) {
        int ge = rowBase + ar_;
        float4 v = make_float4(0.f, 0.f, 0.f, 0.f);
        if (ge < E) v = *(const float4*)&g_xbar[(size_t)ge * 512 + h * 128 + kt + ac4];
        As[ac4 + 0][ar_] = v.x;
        As[ac4 + 1][ar_] = v.y;
        As[ac4 + 2][ar_] = v.z;
        As[ac4 + 3][ar_] = v.w;
        *(float4*)&Bs[br_][bc4] = *(const float4*)&W1[(size_t)(kt + br_) * 256 + h * 64 + bc4];
        __syncthreads();
        #pragma unroll
        for (int k = 0; k < 16; k++) {
            float ar[4], br[4];
            #pragma unroll
            for (int i = 0; i < 4; i++) ar[i] = As[k][ty * 4 + i];
            #pragma unroll
            for (int j = 0; j < 4; j++) br[j] = Bs[k][tx * 4 + j];
            #pragma unroll
            for (int i = 0; i < 4; i++)
                #pragma unroll
                for (int j = 0; j < 4; j++) acc[i][j] += ar[i] * br[j];
        }
        __syncthreads();
    }
    #pragma unroll
    for (int i = 0; i < 4; i++) {
        int ge = rowBase + ty * 4 + i;
        if (ge < E) {
            float4 v = make_float4(acc[i][0], acc[i][1], acc[i][2], acc[i][3]);
            *(float4*)&g_eh[(size_t)ge * 256 + h * 64 + tx * 4] = v;
        }
    }
}

// ---------------- fold att into W1 ----------------
__global__ void attmat_kernel(const float* __restrict__ W1, const float* __restrict__ att) {
    int t = threadIdx.x;           // 512 threads
    int k = t >> 2, h = t & 3;
    const float* wrow = &W1[k * 256 + h * 64];
    const float* a1 = &att[h * 128];
    const float* a2 = &att[h * 128 + 64];
    float s1 = 0.f, s2 = 0.f;
    #pragma unroll
    for (int f = 0; f < 64; f++) {
        float w = wrow[f];
        s1 += w * a1[f];
        s2 += w * a2[f];
    }
    g_A1[k * 4 + h] = s1;
    g_A2[k * 4 + h] = s2;
}

// ---------------- attention logits: ax = x @ A1, ae = hat @ A2 ----------------
__global__ __launch_bounds__(256) void axae_kernel(const float* __restrict__ x,
                                                   const float* __restrict__ hat, int N, int E) {
    __shared__ float sA1[128 * 4], sA2[128 * 4];
    int tid = threadIdx.x;
    for (int i = tid; i < 512; i += 256) { sA1[i] = g_A1[i]; sA2[i] = g_A2[i]; }
    __syncthreads();
    int r = blockIdx.x * 256 + tid;
    if (r >= N + E) return;
    bool isNode = r < N;
    const float4* row = (const float4*)(isNode ? &x[(size_t)r * 128] : &hat[(size_t)(r - N) * 128]);
    const float* Am = isNode ? sA1 : sA2;
    float acc0 = 0.f, acc1 = 0.f, acc2 = 0.f, acc3 = 0.f;
    #pragma unroll
    for (int k4 = 0; k4 < 32; k4++) {
        float4 v = row[k4];
        const float* a = &Am[k4 * 16];
        acc0 += v.x * a[0];  acc1 += v.x * a[1];  acc2 += v.x * a[2];  acc3 += v.x * a[3];
        acc0 += v.y * a[4];  acc1 += v.y * a[5];  acc2 += v.y * a[6];  acc3 += v.y * a[7];
        acc0 += v.z * a[8];  acc1 += v.z * a[9];  acc2 += v.z * a[10]; acc3 += v.z * a[11];
        acc0 += v.w * a[12]; acc1 += v.w * a[13]; acc2 += v.w * a[14]; acc3 += v.w * a[15];
    }
    float* dst = isNode ? &g_ax[r * 4] : &g_ae[(r - N) * 4];
    dst[0] = acc0; dst[1] = acc1; dst[2] = acc2; dst[3] = acc3;
}

// ---------------- conv1 edge stage: segment softmax + per-head x aggregation ----------------
// xbar[e,h,:] = Binv * sum_j alpha[j,h] * x[node_j]; the @W1 happens in gemm_eh afterwards.
#define ECAP 1024
__global__ __launch_bounds__(256) void edge1_kernel(const int* __restrict__ nodeIdx,
                                                    const float* __restrict__ x) {
    int e = blockIdx.x;
    int tid = threadIdx.x;
    int lane = tid & 31, warp = tid >> 5;
    int beg = g_offE[e];
    int k = g_cntE[e];
    float aeh[4];
    #pragma unroll
    for (int h = 0; h < 4; h++) aeh[h] = g_ae[e * 4 + h];

    __shared__ int snode[ECAP];
    __shared__ int sidx[ECAP];
    __shared__ float slog[ECAP * 4];
    __shared__ float4 red[8][128];     // [group][h*32 + f4]
    __shared__ float wr[8][4];
    __shared__ float smax[4], sinv[4];

    float Binv = k > 0 ? 1.f / (float)k : 0.f;
    int f4b = tid & 31;                // float4 index within 128-float x row
    int gg = tid >> 5;                 // 0..7
    float4 a0 = make_float4(0,0,0,0), a1 = a0, a2 = a0, a3 = a0;
    const float4* x4 = (const float4*)x;

    if (k <= ECAP) {
        // ---- phase A: logits + softmax in smem, single alpha write ----
        float lmax[4] = {-1e30f, -1e30f, -1e30f, -1e30f};
        for (int j = tid; j < k; j += 256) {
            int i = g_csrE[beg + j];
            int n = nodeIdx[i];
            sidx[j] = i;
            snode[j] = n;
            #pragma unroll
            for (int h = 0; h < 4; h++) {
                float z = g_ax[n * 4 + h] + aeh[h];
                z = z > 0.f ? z : 0.2f * z;
                slog[j * 4 + h] = z;
                lmax[h] = fmaxf(lmax[h], z);
            }
        }
        #pragma unroll
        for (int o = 16; o; o >>= 1)
            #pragma unroll
            for (int h = 0; h < 4; h++)
                lmax[h] = fmaxf(lmax[h], __shfl_xor_sync(0xffffffffu, lmax[h], o));
        if (lane == 0)
            #pragma unroll
            for (int h = 0; h < 4; h++) wr[warp][h] = lmax[h];
        __syncthreads();
        if (tid < 4) {
            float r = wr[0][tid];
            #pragma unroll
            for (int w2 = 1; w2 < 8; w2++) r = fmaxf(r, wr[w2][tid]);
            smax[tid] = r;
        }
        __syncthreads();

        float lsum[4] = {0.f, 0.f, 0.f, 0.f};
        for (int j = tid; j < k; j += 256) {
            #pragma unroll
            for (int h = 0; h < 4; h++) {
                float ex = __expf(slog[j * 4 + h] - smax[h]);
                slog[j * 4 + h] = ex;
                lsum[h] += ex;
            }
        }
        #pragma unroll
        for (int o = 16; o; o >>= 1)
            #pragma unroll
            for (int h = 0; h < 4; h++) lsum[h] += __shfl_xor_sync(0xffffffffu, lsum[h], o);
        if (lane == 0)
            #pragma unroll
            for (int h = 0; h < 4; h++) wr[warp][h] = lsum[h];
        __syncthreads();
        if (tid < 4) {
            float r = wr[0][tid];
            #pragma unroll
            for (int w2 = 1; w2 < 8; w2++) r += wr[w2][tid];
            sinv[tid] = 1.f / (r + 1e-16f);
        }
        __syncthreads();

        for (int j = tid; j < k; j += 256) {
            float4 a;
            a.x = slog[j * 4 + 0] * sinv[0];
            a.y = slog[j * 4 + 1] * sinv[1];
            a.z = slog[j * 4 + 2] * sinv[2];
            a.w = slog[j * 4 + 3] * sinv[3];
            slog[j * 4 + 0] = a.x; slog[j * 4 + 1] = a.y;
            slog[j * 4 + 2] = a.z; slog[j * 4 + 3] = a.w;
            ((float4*)g_alpha)[sidx[j]] = a;
        }
        __syncthreads();

        // ---- phase B: per-head weighted aggregation of x rows ----
        for (int j = gg; j < k; j += 8) {
            float4 al = ((const float4*)slog)[j];
            float4 xv = x4[(size_t)snode[j] * 32 + f4b];
            a0.x += al.x * xv.x; a0.y += al.x * xv.y; a0.z += al.x * xv.z; a0.w += al.x * xv.w;
            a1.x += al.y * xv.x; a1.y += al.y * xv.y; a1.z += al.y * xv.z; a1.w += al.y * xv.w;
            a2.x += al.z * xv.x; a2.y += al.z * xv.y; a2.z += al.z * xv.z; a2.w += al.z * xv.w;
            a3.x += al.w * xv.x; a3.y += al.w * xv.y; a3.z += al.w * xv.z; a3.w += al.w * xv.w;
        }
    } else {
        // ---- fallback: global alpha staging + chunked aggregation ----
        float lmax[4] = {-1e30f, -1e30f, -1e30f, -1e30f};
        for (int j = tid; j < k; j += 256) {
            int i = g_csrE[beg + j];
            int n = nodeIdx[i];
            #pragma unroll
            for (int h = 0; h < 4; h++) {
                float z = g_ax[n * 4 + h] + aeh[h];
                z = z > 0.f ? z : 0.2f * z;
                g_alpha[i * 4 + h] = z;
                lmax[h] = fmaxf(lmax[h], z);
            }
        }
        #pragma unroll
        for (int o = 16; o; o >>= 1)
            #pragma unroll
            for (int h = 0; h < 4; h++)
                lmax[h] = fmaxf(lmax[h], __shfl_xor_sync(0xffffffffu, lmax[h], o));
        if (lane == 0)
            #pragma unroll
            for (int h = 0; h < 4; h++) wr[warp][h] = lmax[h];
        __syncthreads();
        if (tid < 4) {
            float r = wr[0][tid];
            #pragma unroll
            for (int w2 = 1; w2 < 8; w2++) r = fmaxf(r, wr[w2][tid]);
            smax[tid] = r;
        }
        __syncthreads();
        float lsum[4] = {0.f, 0.f, 0.f, 0.f};
        for (int j = tid; j < k; j += 256) {
            int i = g_csrE[beg + j];
            #pragma unroll
            for (int h = 0; h < 4; h++) {
                float ex = __expf(g_alpha[i * 4 + h] - smax[h]);
                g_alpha[i * 4 + h] = ex;
                lsum[h] += ex;
            }
        }
        #pragma unroll
        for (int o = 16; o; o >>= 1)
            #pragma unroll
            for (int h = 0; h < 4; h++) lsum[h] += __shfl_xor_sync(0xffffffffu, lsum[h], o);
        if (lane == 0)
            #pragma unroll
            for (int h = 0; h < 4; h++) wr[warp][h] = lsum[h];
        __syncthreads();
        if (tid < 4) {
            float r = wr[0][tid];
            #pragma unroll
            for (int w2 = 1; w2 < 8; w2++) r += wr[w2][tid];
            sinv[tid] = 1.f / (r + 1e-16f);
        }
        __syncthreads();
        for (int j = tid; j < k; j += 256) {
            int i = g_csrE[beg + j];
            #pragma unroll
            for (int h = 0; h < 4; h++) g_alpha[i * 4 + h] *= sinv[h];
        }
        __syncthreads();
        for (int base = 0; base < k; base += ECAP) {
            int c = min(ECAP, k - base);
            __syncthreads();
            for (int j = tid; j < c; j += 256) {
                int i = g_csrE[beg + base + j];
                snode[j] = nodeIdx[i];
                ((float4*)slog)[j] = ((const float4*)g_alpha)[i];
            }
            __syncthreads();
            for (int j = gg; j < c; j += 8) {
                float4 al = ((const float4*)slog)[j];
                float4 xv = x4[(size_t)snode[j] * 32 + f4b];
                a0.x += al.x * xv.x; a0.y += al.x * xv.y; a0.z += al.x * xv.z; a0.w += al.x * xv.w;
                a1.x += al.y * xv.x; a1.y += al.y * xv.y; a1.z += al.y * xv.z; a1.w += al.y * xv.w;
                a2.x += al.z * xv.x; a2.y += al.z * xv.y; a2.z += al.z * xv.z; a2.w += al.z * xv.w;
                a3.x += al.w * xv.x; a3.y += al.w * xv.y; a3.z += al.w * xv.z; a3.w += al.w * xv.w;
            }
        }
    }

    // reduce over 8 groups, scale by Binv, write xbar
    red[gg][0 * 32 + f4b] = a0;
    red[gg][1 * 32 + f4b] = a1;
    red[gg][2 * 32 + f4b] = a2;
    red[gg][3 * 32 + f4b] = a3;
    __syncthreads();
    if (tid < 128) {
        float4 r = red[0][tid];
        #pragma unroll
        for (int g2 = 1; g2 < 8; g2++) {
            float4 v = red[g2][tid];
            r.x += v.x; r.y += v.y; r.z += v.z; r.w += v.w;
        }
        r.x *= Binv; r.y *= Binv; r.z *= Binv; r.w *= Binv;
        ((float4*)g_xbar)[(size_t)e * 128 + tid] = r;
    }
}

__device__ __forceinline__ float eluf(float x) { return x > 0.f ? x : expm1f(x); }

// ---------------- conv1 node stage ----------------
__global__ __launch_bounds__(256) void node1_kernel(const int* __restrict__ hedgeIdx,
                                                    const float* __restrict__ b1) {
    int n = blockIdx.x;
    int tid = threadIdx.x;
    int beg = g_offN[n];
    int d = g_cntN[n];
    int end = beg + d;
    float Dinv = d > 0 ? 1.f / (float)d : 0.f;
    int g = tid >> 6, f4 = tid & 63, h = f4 >> 4;
    float4 acc = make_float4(0.f, 0.f, 0.f, 0.f);
    const float4* eh4 = (const float4*)g_eh;
    for (int j = beg + g; j < end; j += 4) {
        int i = g_csrN[j];
        int e = hedgeIdx[i];
        float a = g_alpha[i * 4 + h];
        float4 ev = eh4[e * 64 + f4];
        acc.x += a * ev.x; acc.y += a * ev.y; acc.z += a * ev.z; acc.w += a * ev.w;
    }
    __shared__ float4 racc[256];
    racc[tid] = acc;
    __syncthreads();
    if (tid < 64) {
        float4 a = racc[tid], b = racc[tid + 64], c2 = racc[tid + 128], d2 = racc[tid + 192];
        float4 bv = ((const float4*)b1)[tid];
        float4 r;
        r.x = eluf((a.x + b.x + c2.x + d2.x) * Dinv + bv.x);
        r.y = eluf((a.y + b.y + c2.y + d2.y) * Dinv + bv.y);
        r.z = eluf((a.z + b.z + c2.z + d2.z) * Dinv + bv.z);
        r.w = eluf((a.w + b.w + c2.w + d2.w) * Dinv + bv.w);
        ((float4*)g_h)[n * 64 + tid] = r;
    }
}

// ---------------- conv2 ----------------
__global__ __launch_bounds__(256) void edge2_kernel(const int* __restrict__ nodeIdx) {
    int e = blockIdx.x;
    int tid = threadIdx.x;
    int beg = g_offE[e];
    int k = g_cntE[e];
    int end = beg + k;
    float Binv = k > 0 ? 1.f / (float)k : 0.f;
    int g = tid >> 6, f = tid & 63;
    float acc = 0.f;
    for (int j = beg + g; j < end; j += 4) {
        int i = g_csrE[j];
        int n = nodeIdx[i];
        acc += g_xh2[(size_t)n * 64 + f];
    }
    __shared__ float racc[256];
    racc[tid] = acc;
    __syncthreads();
    if (tid < 64)
        g_eh2[e * 64 + tid] = (racc[tid] + racc[tid + 64] + racc[tid + 128] + racc[tid + 192]) * Binv;
}

__global__ __launch_bounds__(256) void node2_kernel(const int* __restrict__ hedgeIdx,
                                                    const float* __restrict__ b2,
                                                    float* __restrict__ out, int N) {
    int warp = threadIdx.x >> 5, lane = threadIdx.x & 31;
    int n = blockIdx.x * 8 + warp;
    if (n >= N) return;
    int beg = g_offN[n];
    int d = g_cntN[n];
    float Dinv = d > 0 ? 1.f / (float)d : 0.f;
    const float2* eh2 = (const float2*)g_eh2;
    float ax = 0.f, ay = 0.f;
    int j = beg, end = beg + d;
    for (; j + 1 < end; j += 2) {
        int i0 = g_csrN[j], i1 = g_csrN[j + 1];
        int e0 = hedgeIdx[i0], e1 = hedgeIdx[i1];
        float2 v0 = eh2[e0 * 32 + lane];
        float2 v1 = eh2[e1 * 32 + lane];
        ax += v0.x + v1.x; ay += v0.y + v1.y;
    }
    if (j < end) {
        int i = g_csrN[j];
        int e = hedgeIdx[i];
        float2 v = eh2[e * 32 + lane];
        ax += v.x; ay += v.y;
    }
    float2 bb = ((const float2*)b2)[lane];
    ((float2*)out)[(size_t)n * 32 + lane] = make_float2(ax * Dinv + bb.x, ay * Dinv + bb.y);
}

// ---------------- launch ----------------
extern "C" void kernel_launch(void* const* d_in, const int* in_sizes, int n_in,
                              void* d_out, int out_size) {
    const float* x    = (const float*)d_in[0];
    const int*   ei   = (const int*)d_in[1];
    const float* hat  = (const float*)d_in[2];
    const float* W1   = (const float*)d_in[3];
    const float* att1 = (const float*)d_in[4];
    const float* b1   = (const float*)d_in[5];
    const float* W2   = (const float*)d_in[6];
    const float* b2   = (const float*)d_in[7];
    float* out = (float*)d_out;

    int N   = in_sizes[0] / 128;
    int NNZ = in_sizes[1] / 2;
    int E   = in_sizes[2] / 128;
    const int* node  = ei;
    const int* hedge = ei + NNZ;

    float *p_h, *p_xh2;
    cudaGetSymbolAddress((void**)&p_h, g_h);
    cudaGetSymbolAddress((void**)&p_xh2, g_xh2);

    // lazy one-time side stream + events (host objects only)
    static cudaStream_t s1 = nullptr;
    static cudaEvent_t evFork = nullptr, evJoin = nullptr;
    if (s1 == nullptr) {
        cudaStreamCreateWithFlags(&s1, cudaStreamNonBlocking);
        cudaEventCreateWithFlags(&evFork, cudaEventDisableTiming);
        cudaEventCreateWithFlags(&evJoin, cudaEventDisableTiming);
    }

    cudaEventRecord(evFork, 0);
    cudaStreamWaitEvent(s1, evFork, 0);

    // main stream: CSR build; side stream: attention logits (independent)
    zero_counts_kernel<<<128, 256>>>(N, E);
    count_kernel<<<480, 256>>>(node, hedge, NNZ);
    attmat_kernel<<<1, 512, 0, s1>>>(W1, att1);
    axae_kernel<<<(N + E + 255) / 256, 256, 0, s1>>>(x, hat, N, E);
    cudaEventRecord(evJoin, s1);
    alloc_kernel<<<64, 256>>>(N, E);
    scatter_kernel<<<480, 256>>>(node, hedge, NNZ);
    cudaStreamWaitEvent(0, evJoin, 0);

    // conv1: softmax + per-head x aggregation, then (aggregate @ W1), then node stage
    edge1_kernel<<<E, 256>>>(node, x);
    gemm_eh_kernel<<<dim3((E + 63) / 64, 4), 256>>>(W1, E);
    node1_kernel<<<N, 256>>>(hedge, b1);

    // conv2
    sgemm_kernel<128, 64, 16, 8, 4><<<dim3((N + 127) / 128, 1), 256>>>(p_h, W2, p_xh2, N, 64, 256);
    edge2_kernel<<<E, 256>>>(node);
    node2_kernel<<<(N + 7) / 8, 256>>>(hedge, b2, out, N);
}

// round 11
// speedup vs baseline: 1.2437x; 1.2437x over previous
#include <cuda_runtime.h>
#include <math.h>
#include <cstdint>

#define MAXN   50000
#define MAXE   10000
#define MAXNNZ 600000

// ---------------- scratch (static __device__, no allocations) ----------------
__device__ float g_xh[MAXN * 256];    // x @ W1
__device__ float g_ax[MAXN * 4];
__device__ float g_ae[MAXE * 4];
__device__ float g_A1[128 * 4];
__device__ float g_A2[128 * 4];
__device__ float g_alpha[MAXNNZ * 4];
__device__ float g_eh[MAXE * 256];
__device__ float g_h[MAXN * 256];
__device__ float g_xh2[MAXN * 64];
__device__ float g_eh2[MAXE * 64];
__device__ int g_cntN[MAXN], g_cntE[MAXE];
__device__ int g_curN[MAXN], g_curE[MAXE];
__device__ int g_offN[MAXN], g_offE[MAXE];
__device__ int g_csrN[MAXNNZ], g_csrE[MAXNNZ];
__device__ int g_totN, g_totE;

// ---------------- CSR construction ----------------
__global__ void zero_counts_kernel(int N, int E) {
    int i = blockIdx.x * blockDim.x + threadIdx.x;
    int s = gridDim.x * blockDim.x;
    if (i == 0) { g_totN = 0; g_totE = 0; }
    for (int j = i; j < N; j += s) { g_cntN[j] = 0; g_curN[j] = 0; }
    for (int j = i; j < E; j += s) { g_cntE[j] = 0; g_curE[j] = 0; }
}

__global__ void count_kernel(const int* __restrict__ node, const int* __restrict__ hedge, int nnz) {
    int t = blockIdx.x * blockDim.x + threadIdx.x;
    int stride4 = gridDim.x * blockDim.x * 4;
    for (int j0 = t * 4; j0 < nnz; j0 += stride4) {
        if (j0 + 3 < nnz) {
            int4 n4 = *(const int4*)&node[j0];
            int4 h4 = *(const int4*)&hedge[j0];
            atomicAdd(&g_cntN[n4.x], 1); atomicAdd(&g_cntN[n4.y], 1);
            atomicAdd(&g_cntN[n4.z], 1); atomicAdd(&g_cntN[n4.w], 1);
            atomicAdd(&g_cntE[h4.x], 1); atomicAdd(&g_cntE[h4.y], 1);
            atomicAdd(&g_cntE[h4.z], 1); atomicAdd(&g_cntE[h4.w], 1);
        } else {
            for (int j = j0; j < nnz; j++) {
                atomicAdd(&g_cntN[node[j]], 1);
                atomicAdd(&g_cntE[hedge[j]], 1);
            }
        }
    }
}

__device__ __forceinline__ void alloc_ranges(const int* __restrict__ cnt, int* __restrict__ off,
                                             int* total, int n, int gwarp, int nwarps, int lane) {
    for (int j0 = gwarp * 32; j0 < n; j0 += nwarps * 32) {
        int j = j0 + lane;
        int c = (j < n) ? cnt[j] : 0;
        int x = c;
        #pragma unroll
        for (int o = 1; o < 32; o <<= 1) {
            int y = __shfl_up_sync(0xffffffffu, x, o);
            if (lane >= o) x += y;
        }
        int wtot = __shfl_sync(0xffffffffu, x, 31);
        int base = 0;
        if (lane == 0) base = atomicAdd(total, wtot);
        base = __shfl_sync(0xffffffffu, base, 0);
        if (j < n) off[j] = base + x - c;
    }
}

__global__ void alloc_kernel(int N, int E) {
    int t = blockIdx.x * blockDim.x + threadIdx.x;
    int gwarp = t >> 5, lane = t & 31;
    int nwarps = (gridDim.x * blockDim.x) >> 5;
    alloc_ranges(g_cntN, g_offN, &g_totN, N, gwarp, nwarps, lane);
    alloc_ranges(g_cntE, g_offE, &g_totE, E, gwarp, nwarps, lane);
}

__global__ void scatter_kernel(const int* __restrict__ node, const int* __restrict__ hedge, int nnz) {
    int t = blockIdx.x * blockDim.x + threadIdx.x;
    int stride4 = gridDim.x * blockDim.x * 4;
    for (int j0 = t * 4; j0 < nnz; j0 += stride4) {
        if (j0 + 3 < nnz) {
            int4 n4 = *(const int4*)&node[j0];
            int4 h4 = *(const int4*)&hedge[j0];
            g_csrN[g_offN[n4.x] + atomicAdd(&g_curN[n4.x], 1)] = j0 + 0;
            g_csrN[g_offN[n4.y] + atomicAdd(&g_curN[n4.y], 1)] = j0 + 1;
            g_csrN[g_offN[n4.z] + atomicAdd(&g_curN[n4.z], 1)] = j0 + 2;
            g_csrN[g_offN[n4.w] + atomicAdd(&g_curN[n4.w], 1)] = j0 + 3;
            g_csrE[g_offE[h4.x] + atomicAdd(&g_curE[h4.x], 1)] = j0 + 0;
            g_csrE[g_offE[h4.y] + atomicAdd(&g_curE[h4.y], 1)] = j0 + 1;
            g_csrE[g_offE[h4.z] + atomicAdd(&g_curE[h4.z], 1)] = j0 + 2;
            g_csrE[g_offE[h4.w] + atomicAdd(&g_curE[h4.w], 1)] = j0 + 3;
        } else {
            for (int j = j0; j < nnz; j++) {
                int n = node[j], h = hedge[j];
                g_csrN[g_offN[n] + atomicAdd(&g_curN[n], 1)] = j;
                g_csrE[g_offE[h] + atomicAdd(&g_curE[h], 1)] = j;
            }
        }
    }
}

// ---------------- tiled fp32 GEMM (round-5 version): C[M,N] = A[M,K] @ B[K,N] ----------------
template <int BM, int BN, int BK, int TM, int TN>
__global__ __launch_bounds__(256) void sgemm_kernel(const float* __restrict__ A,
                                                    const float* __restrict__ B,
                                                    float* __restrict__ C, int M, int N, int K) {
    constexpr int THREADS = (BM / TM) * (BN / TN);
    __shared__ float As[BK][BM];
    __shared__ float Bs[BK][BN];
    int tid = threadIdx.x;
    int tx = tid % (BN / TN);
    int ty = tid / (BN / TN);
    int rowBase = blockIdx.x * BM;
    int colBase = blockIdx.y * BN;
    float acc[TM][TN] = {};
    for (int kt = 0; kt < K; kt += BK) {
        #pragma unroll
        for (int l = tid; l < BM * BK / 4; l += THREADS) {
            int r = l / (BK / 4), c4 = l % (BK / 4);
            int gr = rowBase + r;
            float4 v = make_float4(0.f, 0.f, 0.f, 0.f);
            if (gr < M) v = *(const float4*)&A[(size_t)gr * K + kt + c4 * 4];
            As[c4 * 4 + 0][r] = v.x;
            As[c4 * 4 + 1][r] = v.y;
            As[c4 * 4 + 2][r] = v.z;
            As[c4 * 4 + 3][r] = v.w;
        }
        #pragma unroll
        for (int l = tid; l < BK * BN / 4; l += THREADS) {
            int r = l / (BN / 4), c4 = l % (BN / 4);
            *(float4*)&Bs[r][c4 * 4] = *(const float4*)&B[(size_t)(kt + r) * N + colBase + c4 * 4];
        }
        __syncthreads();
        #pragma unroll
        for (int k = 0; k < BK; k++) {
            float ar[TM], br[TN];
            #pragma unroll
            for (int i = 0; i < TM; i++) ar[i] = As[k][ty * TM + i];
            #pragma unroll
            for (int j = 0; j < TN; j++) br[j] = Bs[k][tx * TN + j];
            #pragma unroll
            for (int i = 0; i < TM; i++)
                #pragma unroll
                for (int j = 0; j < TN; j++) acc[i][j] += ar[i] * br[j];
        }
        __syncthreads();
    }
    #pragma unroll
    for (int i = 0; i < TM; i++) {
        int gr = rowBase + ty * TM + i;
        if (gr < M) {
            #pragma unroll
            for (int j4 = 0; j4 < TN / 4; j4++) {
                float4 v = make_float4(acc[i][j4 * 4 + 0], acc[i][j4 * 4 + 1],
                                       acc[i][j4 * 4 + 2], acc[i][j4 * 4 + 3]);
                *(float4*)&C[(size_t)gr * N + colBase + tx * TN + j4 * 4] = v;
            }
        }
    }
}

// ---------------- fold att into W1 ----------------
__global__ void attmat_kernel(const float* __restrict__ W1, const float* __restrict__ att) {
    int t = threadIdx.x;           // 512 threads
    int k = t >> 2, h = t & 3;
    const float* wrow = &W1[k * 256 + h * 64];
    const float* a1 = &att[h * 128];
    const float* a2 = &att[h * 128 + 64];
    float s1 = 0.f, s2 = 0.f;
    #pragma unroll
    for (int f = 0; f < 64; f++) {
        float w = wrow[f];
        s1 += w * a1[f];
        s2 += w * a2[f];
    }
    g_A1[k * 4 + h] = s1;
    g_A2[k * 4 + h] = s2;
}

// ---------------- attention logits: ax = x @ A1, ae = hat @ A2 ----------------
__global__ __launch_bounds__(256) void axae_kernel(const float* __restrict__ x,
                                                   const float* __restrict__ hat, int N, int E) {
    __shared__ float sA1[128 * 4], sA2[128 * 4];
    int tid = threadIdx.x;
    for (int i = tid; i < 512; i += 256) { sA1[i] = g_A1[i]; sA2[i] = g_A2[i]; }
    __syncthreads();
    int r = blockIdx.x * 256 + tid;
    if (r >= N + E) return;
    bool isNode = r < N;
    const float4* row = (const float4*)(isNode ? &x[(size_t)r * 128] : &hat[(size_t)(r - N) * 128]);
    const float* Am = isNode ? sA1 : sA2;
    float acc0 = 0.f, acc1 = 0.f, acc2 = 0.f, acc3 = 0.f;
    #pragma unroll
    for (int k4 = 0; k4 < 32; k4++) {
        float4 v = row[k4];
        const float* a = &Am[k4 * 16];
        acc0 += v.x * a[0];  acc1 += v.x * a[1];  acc2 += v.x * a[2];  acc3 += v.x * a[3];
        acc0 += v.y * a[4];  acc1 += v.y * a[5];  acc2 += v.y * a[6];  acc3 += v.y * a[7];
        acc0 += v.z * a[8];  acc1 += v.z * a[9];  acc2 += v.z * a[10]; acc3 += v.z * a[11];
        acc0 += v.w * a[12]; acc1 += v.w * a[13]; acc2 += v.w * a[14]; acc3 += v.w * a[15];
    }
    float* dst = isNode ? &g_ax[r * 4] : &g_ae[(r - N) * 4];
    dst[0] = acc0; dst[1] = acc1; dst[2] = acc2; dst[3] = acc3;
}

// ---------------- conv1 edge stage: segment softmax + propagate 1 ----------------
#define ECAP 1024
__global__ __launch_bounds__(256) void edge1_kernel(const int* __restrict__ nodeIdx) {
    int e = blockIdx.x;
    int tid = threadIdx.x;
    int lane = tid & 31, warp = tid >> 5;
    int beg = g_offE[e];
    int k = g_cntE[e];
    float aeh[4];
    #pragma unroll
    for (int h = 0; h < 4; h++) aeh[h] = g_ae[e * 4 + h];

    __shared__ int snode[ECAP];
    __shared__ int sidx[ECAP];
    __shared__ float slog[ECAP * 4];
    __shared__ float4 racc[256];
    __shared__ float wr[8][4];
    __shared__ float smax[4], sinv[4];

    int g = tid >> 6, f4 = tid & 63, hh = f4 >> 4;
    float Binv = k > 0 ? 1.f / (float)k : 0.f;
    float4 acc = make_float4(0.f, 0.f, 0.f, 0.f);
    const float4* xh4 = (const float4*)g_xh;

    if (k <= ECAP) {
        float lmax[4] = {-1e30f, -1e30f, -1e30f, -1e30f};
        for (int j = tid; j < k; j += 256) {
            int i = g_csrE[beg + j];
            int n = nodeIdx[i];
            sidx[j] = i;
            snode[j] = n;
            #pragma unroll
            for (int h = 0; h < 4; h++) {
                float z = g_ax[n * 4 + h] + aeh[h];
                z = z > 0.f ? z : 0.2f * z;
                slog[j * 4 + h] = z;
                lmax[h] = fmaxf(lmax[h], z);
            }
        }
        #pragma unroll
        for (int o = 16; o; o >>= 1)
            #pragma unroll
            for (int h = 0; h < 4; h++)
                lmax[h] = fmaxf(lmax[h], __shfl_xor_sync(0xffffffffu, lmax[h], o));
        if (lane == 0)
            #pragma unroll
            for (int h = 0; h < 4; h++) wr[warp][h] = lmax[h];
        __syncthreads();
        if (tid < 4) {
            float r = wr[0][tid];
            #pragma unroll
            for (int w2 = 1; w2 < 8; w2++) r = fmaxf(r, wr[w2][tid]);
            smax[tid] = r;
        }
        __syncthreads();

        float lsum[4] = {0.f, 0.f, 0.f, 0.f};
        for (int j = tid; j < k; j += 256) {
            #pragma unroll
            for (int h = 0; h < 4; h++) {
                float ex = __expf(slog[j * 4 + h] - smax[h]);
                slog[j * 4 + h] = ex;
                lsum[h] += ex;
            }
        }
        #pragma unroll
        for (int o = 16; o; o >>= 1)
            #pragma unroll
            for (int h = 0; h < 4; h++) lsum[h] += __shfl_xor_sync(0xffffffffu, lsum[h], o);
        if (lane == 0)
            #pragma unroll
            for (int h = 0; h < 4; h++) wr[warp][h] = lsum[h];
        __syncthreads();
        if (tid < 4) {
            float r = wr[0][tid];
            #pragma unroll
            for (int w2 = 1; w2 < 8; w2++) r += wr[w2][tid];
            sinv[tid] = 1.f / (r + 1e-16f);
        }
        __syncthreads();

        for (int j = tid; j < k; j += 256) {
            float4 a;
            a.x = slog[j * 4 + 0] * sinv[0];
            a.y = slog[j * 4 + 1] * sinv[1];
            a.z = slog[j * 4 + 2] * sinv[2];
            a.w = slog[j * 4 + 3] * sinv[3];
            slog[j * 4 + 0] = a.x; slog[j * 4 + 1] = a.y;
            slog[j * 4 + 2] = a.z; slog[j * 4 + 3] = a.w;
            ((float4*)g_alpha)[sidx[j]] = a;
        }
        __syncthreads();

        for (int j = g; j < k; j += 4) {
            float a = slog[j * 4 + hh];
            float4 xv = xh4[snode[j] * 64 + f4];
            acc.x += a * xv.x; acc.y += a * xv.y; acc.z += a * xv.z; acc.w += a * xv.w;
        }
    } else {
        float lmax[4] = {-1e30f, -1e30f, -1e30f, -1e30f};
        for (int j = tid; j < k; j += 256) {
            int i = g_csrE[beg + j];
            int n = nodeIdx[i];
            #pragma unroll
            for (int h = 0; h < 4; h++) {
                float z = g_ax[n * 4 + h] + aeh[h];
                z = z > 0.f ? z : 0.2f * z;
                g_alpha[i * 4 + h] = z;
                lmax[h] = fmaxf(lmax[h], z);
            }
        }
        #pragma unroll
        for (int o = 16; o; o >>= 1)
            #pragma unroll
            for (int h = 0; h < 4; h++)
                lmax[h] = fmaxf(lmax[h], __shfl_xor_sync(0xffffffffu, lmax[h], o));
        if (lane == 0)
            #pragma unroll
            for (int h = 0; h < 4; h++) wr[warp][h] = lmax[h];
        __syncthreads();
        if (tid < 4) {
            float r = wr[0][tid];
            #pragma unroll
            for (int w2 = 1; w2 < 8; w2++) r = fmaxf(r, wr[w2][tid]);
            smax[tid] = r;
        }
        __syncthreads();
        float lsum[4] = {0.f, 0.f, 0.f, 0.f};
        for (int j = tid; j < k; j += 256) {
            int i = g_csrE[beg + j];
            #pragma unroll
            for (int h = 0; h < 4; h++) {
                float ex = __expf(g_alpha[i * 4 + h] - smax[h]);
                g_alpha[i * 4 + h] = ex;
                lsum[h] += ex;
            }
        }
        #pragma unroll
        for (int o = 16; o; o >>= 1)
            #pragma unroll
            for (int h = 0; h < 4; h++) lsum[h] += __shfl_xor_sync(0xffffffffu, lsum[h], o);
        if (lane == 0)
            #pragma unroll
            for (int h = 0; h < 4; h++) wr[warp][h] = lsum[h];
        __syncthreads();
        if (tid < 4) {
            float r = wr[0][tid];
            #pragma unroll
            for (int w2 = 1; w2 < 8; w2++) r += wr[w2][tid];
            sinv[tid] = 1.f / (r + 1e-16f);
        }
        __syncthreads();
        for (int j = tid; j < k; j += 256) {
            int i = g_csrE[beg + j];
            #pragma unroll
            for (int h = 0; h < 4; h++) g_alpha[i * 4 + h] *= sinv[h];
        }
        __syncthreads();
        for (int base = 0; base < k; base += ECAP) {
            int c = min(ECAP, k - base);
            __syncthreads();
            for (int j = tid; j < c; j += 256) {
                int i = g_csrE[beg + base + j];
                snode[j] = nodeIdx[i];
                ((float4*)slog)[j] = ((const float4*)g_alpha)[i];
            }
            __syncthreads();
            for (int j = g; j < c; j += 4) {
                float a = slog[j * 4 + hh];
                float4 xv = xh4[snode[j] * 64 + f4];
                acc.x += a * xv.x; acc.y += a * xv.y; acc.z += a * xv.z; acc.w += a * xv.w;
            }
        }
    }

    racc[tid] = acc;
    __syncthreads();
    if (tid < 64) {
        float4 a = racc[tid], b = racc[tid + 64], c2 = racc[tid + 128], d2 = racc[tid + 192];
        float4 r;
        r.x = (a.x + b.x + c2.x + d2.x) * Binv;
        r.y = (a.y + b.y + c2.y + d2.y) * Binv;
        r.z = (a.z + b.z + c2.z + d2.z) * Binv;
        r.w = (a.w + b.w + c2.w + d2.w) * Binv;
        ((float4*)g_eh)[e * 64 + tid] = r;
    }
}

__device__ __forceinline__ float eluf(float x) { return x > 0.f ? x : expm1f(x); }

// ---------------- conv1 node stage (2-way unrolled gather for MLP) ----------------
__global__ __launch_bounds__(256) void node1_kernel(const int* __restrict__ hedgeIdx,
                                                    const float* __restrict__ b1) {
    int n = blockIdx.x;
    int tid = threadIdx.x;
    int beg = g_offN[n];
    int d = g_cntN[n];
    int end = beg + d;
    float Dinv = d > 0 ? 1.f / (float)d : 0.f;
    int g = tid >> 6, f4 = tid & 63, h = f4 >> 4;
    float4 acc = make_float4(0.f, 0.f, 0.f, 0.f);
    const float4* eh4 = (const float4*)g_eh;
    int j = beg + g;
    for (; j + 4 < end; j += 8) {
        int i0 = g_csrN[j], i1 = g_csrN[j + 4];
        int e0 = hedgeIdx[i0], e1 = hedgeIdx[i1];
        float a0 = g_alpha[i0 * 4 + h], a1 = g_alpha[i1 * 4 + h];
        float4 v0 = eh4[e0 * 64 + f4];
        float4 v1 = eh4[e1 * 64 + f4];
        acc.x += a0 * v0.x + a1 * v1.x;
        acc.y += a0 * v0.y + a1 * v1.y;
        acc.z += a0 * v0.z + a1 * v1.z;
        acc.w += a0 * v0.w + a1 * v1.w;
    }
    if (j < end) {
        int i = g_csrN[j];
        int e = hedgeIdx[i];
        float a = g_alpha[i * 4 + h];
        float4 ev = eh4[e * 64 + f4];
        acc.x += a * ev.x; acc.y += a * ev.y; acc.z += a * ev.z; acc.w += a * ev.w;
    }
    __shared__ float4 racc[256];
    racc[tid] = acc;
    __syncthreads();
    if (tid < 64) {
        float4 a = racc[tid], b = racc[tid + 64], c2 = racc[tid + 128], d2 = racc[tid + 192];
        float4 bv = ((const float4*)b1)[tid];
        float4 r;
        r.x = eluf((a.x + b.x + c2.x + d2.x) * Dinv + bv.x);
        r.y = eluf((a.y + b.y + c2.y + d2.y) * Dinv + bv.y);
        r.z = eluf((a.z + b.z + c2.z + d2.z) * Dinv + bv.z);
        r.w = eluf((a.w + b.w + c2.w + d2.w) * Dinv + bv.w);
        ((float4*)g_h)[n * 64 + tid] = r;
    }
}

// ---------------- conv2 ----------------
__global__ __launch_bounds__(256) void edge2_kernel(const int* __restrict__ nodeIdx) {
    int e = blockIdx.x;
    int tid = threadIdx.x;
    int beg = g_offE[e];
    int k = g_cntE[e];
    int end = beg + k;
    float Binv = k > 0 ? 1.f / (float)k : 0.f;
    int g = tid >> 6, f = tid & 63;
    float acc = 0.f;
    for (int j = beg + g; j < end; j += 4) {
        int i = g_csrE[j];
        int n = nodeIdx[i];
        acc += g_xh2[(size_t)n * 64 + f];
    }
    __shared__ float racc[256];
    racc[tid] = acc;
    __syncthreads();
    if (tid < 64)
        g_eh2[e * 64 + tid] = (racc[tid] + racc[tid + 64] + racc[tid + 128] + racc[tid + 192]) * Binv;
}

__global__ __launch_bounds__(256) void node2_kernel(const int* __restrict__ hedgeIdx,
                                                    const float* __restrict__ b2,
                                                    float* __restrict__ out, int N) {
    int warp = threadIdx.x >> 5, lane = threadIdx.x & 31;
    int n = blockIdx.x * 8 + warp;
    if (n >= N) return;
    int beg = g_offN[n];
    int d = g_cntN[n];
    float Dinv = d > 0 ? 1.f / (float)d : 0.f;
    const float2* eh2 = (const float2*)g_eh2;
    float ax = 0.f, ay = 0.f;
    int j = beg, end = beg + d;
    for (; j + 1 < end; j += 2) {
        int i0 = g_csrN[j], i1 = g_csrN[j + 1];
        int e0 = hedgeIdx[i0], e1 = hedgeIdx[i1];
        float2 v0 = eh2[e0 * 32 + lane];
        float2 v1 = eh2[e1 * 32 + lane];
        ax += v0.x + v1.x; ay += v0.y + v1.y;
    }
    if (j < end) {
        int i = g_csrN[j];
        int e = hedgeIdx[i];
        float2 v = eh2[e * 32 + lane];
        ax += v.x; ay += v.y;
    }
    float2 bb = ((const float2*)b2)[lane];
    ((float2*)out)[(size_t)n * 32 + lane] = make_float2(ax * Dinv + bb.x, ay * Dinv + bb.y);
}

// ---------------- launch ----------------
extern "C" void kernel_launch(void* const* d_in, const int* in_sizes, int n_in,
                              void* d_out, int out_size) {
    const float* x    = (const float*)d_in[0];
    const int*   ei   = (const int*)d_in[1];
    const float* hat  = (const float*)d_in[2];
    const float* W1   = (const float*)d_in[3];
    const float* att1 = (const float*)d_in[4];
    const float* b1   = (const float*)d_in[5];
    const float* W2   = (const float*)d_in[6];
    const float* b2   = (const float*)d_in[7];
    float* out = (float*)d_out;

    int N   = in_sizes[0] / 128;
    int NNZ = in_sizes[1] / 2;
    int E   = in_sizes[2] / 128;
    const int* node  = ei;
    const int* hedge = ei + NNZ;

    float *p_xh, *p_h, *p_xh2;
    cudaGetSymbolAddress((void**)&p_xh, g_xh);
    cudaGetSymbolAddress((void**)&p_h, g_h);
    cudaGetSymbolAddress((void**)&p_xh2, g_xh2);

    // lazy one-time side stream + events (host objects only)
    static cudaStream_t s1 = nullptr;
    static cudaEvent_t evFork = nullptr, evJoin = nullptr;
    if (s1 == nullptr) {
        cudaStreamCreateWithFlags(&s1, cudaStreamNonBlocking);
        cudaEventCreateWithFlags(&evFork, cudaEventDisableTiming);
        cudaEventCreateWithFlags(&evJoin, cudaEventDisableTiming);
    }

    // fork: side stream runs ONLY the big GEMM (96us); main runs CSR + attention
    // logits (~70us) — balanced fork shortens the join point.
    cudaEventRecord(evFork, 0);
    cudaStreamWaitEvent(s1, evFork, 0);

    zero_counts_kernel<<<128, 256>>>(N, E);                                         // 0 (main)
    count_kernel<<<480, 256>>>(node, hedge, NNZ);                                   // 1 (main)
    sgemm_kernel<128, 128, 16, 8, 8><<<dim3((N + 127) / 128, 2), 256, 0, s1>>>(x, W1, p_xh, N, 256, 128); // 2 (side)
    alloc_kernel<<<64, 256>>>(N, E);                                                // 3 (main, profiled)
    scatter_kernel<<<480, 256>>>(node, hedge, NNZ);                                 // main
    attmat_kernel<<<1, 512>>>(W1, att1);                                            // main
    axae_kernel<<<(N + E + 255) / 256, 256>>>(x, hat, N, E);                        // main
    cudaEventRecord(evJoin, s1);

    // join
    cudaStreamWaitEvent(0, evJoin, 0);

    // conv1: softmax + propagate 1 + node stage
    edge1_kernel<<<E, 256>>>(node);
    node1_kernel<<<N, 256>>>(hedge, b1);

    // conv2
    sgemm_kernel<128, 64, 16, 8, 4><<<dim3((N + 127) / 128, 1), 256>>>(p_h, W2, p_xh2, N, 64, 256);
    edge2_kernel<<<E, 256>>>(node);
    node2_kernel<<<(N + 7) / 8, 256>>>(hedge, b2, out, N);
}

// round 12
// speedup vs baseline: 1.3959x; 1.1223x over previous
#include <cuda_runtime.h>
#include <cuda_fp16.h>
#include <math.h>
#include <cstdint>

#define MAXN   50000
#define MAXE   10000
#define MAXNNZ 600000

// ---------------- scratch (static __device__, no allocations) ----------------
__device__ __half g_xh_h[MAXN * 256];  // x @ W1, fp16 storage (consumed only by edge1)
__device__ __half g_eh_h[MAXE * 256];  // propagate-1 output, fp16 storage (consumed only by node1)
__device__ float g_ax[MAXN * 4];
__device__ float g_ae[MAXE * 4];
__device__ float g_A1[128 * 4];
__device__ float g_A2[128 * 4];
__device__ float g_alpha[MAXNNZ * 4];
__device__ float g_h[MAXN * 256];
__device__ float g_xh2[MAXN * 64];
__device__ float g_eh2[MAXE * 64];
__device__ int g_cntN[MAXN], g_cntE[MAXE];
__device__ int g_curN[MAXN], g_curE[MAXE];
__device__ int g_offN[MAXN], g_offE[MAXE];
__device__ int g_csrN[MAXNNZ], g_csrE[MAXNNZ];
__device__ int g_totN, g_totE;

__device__ __forceinline__ float4 h4_to_f4(uint2 raw) {
    __half2 h0 = *(__half2*)&raw.x;
    __half2 h1 = *(__half2*)&raw.y;
    float2 a = __half22float2(h0), b = __half22float2(h1);
    return make_float4(a.x, a.y, b.x, b.y);
}
__device__ __forceinline__ uint2 f4_to_h4(float4 v) {
    __half2 h0 = __floats2half2_rn(v.x, v.y);
    __half2 h1 = __floats2half2_rn(v.z, v.w);
    uint2 r;
    r.x = *(uint32_t*)&h0;
    r.y = *(uint32_t*)&h1;
    return r;
}

// ---------------- CSR construction ----------------
__global__ void zero_counts_kernel(int N, int E) {
    int i = blockIdx.x * blockDim.x + threadIdx.x;
    int s = gridDim.x * blockDim.x;
    if (i == 0) { g_totN = 0; g_totE = 0; }
    for (int j = i; j < N; j += s) { g_cntN[j] = 0; g_curN[j] = 0; }
    for (int j = i; j < E; j += s) { g_cntE[j] = 0; g_curE[j] = 0; }
}

__global__ void count_kernel(const int* __restrict__ node, const int* __restrict__ hedge, int nnz) {
    int t = blockIdx.x * blockDim.x + threadIdx.x;
    int stride4 = gridDim.x * blockDim.x * 4;
    for (int j0 = t * 4; j0 < nnz; j0 += stride4) {
        if (j0 + 3 < nnz) {
            int4 n4 = *(const int4*)&node[j0];
            int4 h4 = *(const int4*)&hedge[j0];
            atomicAdd(&g_cntN[n4.x], 1); atomicAdd(&g_cntN[n4.y], 1);
            atomicAdd(&g_cntN[n4.z], 1); atomicAdd(&g_cntN[n4.w], 1);
            atomicAdd(&g_cntE[h4.x], 1); atomicAdd(&g_cntE[h4.y], 1);
            atomicAdd(&g_cntE[h4.z], 1); atomicAdd(&g_cntE[h4.w], 1);
        } else {
            for (int j = j0; j < nnz; j++) {
                atomicAdd(&g_cntN[node[j]], 1);
                atomicAdd(&g_cntE[hedge[j]], 1);
            }
        }
    }
}

__device__ __forceinline__ void alloc_ranges(const int* __restrict__ cnt, int* __restrict__ off,
                                             int* total, int n, int gwarp, int nwarps, int lane) {
    for (int j0 = gwarp * 32; j0 < n; j0 += nwarps * 32) {
        int j = j0 + lane;
        int c = (j < n) ? cnt[j] : 0;
        int x = c;
        #pragma unroll
        for (int o = 1; o < 32; o <<= 1) {
            int y = __shfl_up_sync(0xffffffffu, x, o);
            if (lane >= o) x += y;
        }
        int wtot = __shfl_sync(0xffffffffu, x, 31);
        int base = 0;
        if (lane == 0) base = atomicAdd(total, wtot);
        base = __shfl_sync(0xffffffffu, base, 0);
        if (j < n) off[j] = base + x - c;
    }
}

__global__ void alloc_kernel(int N, int E) {
    int t = blockIdx.x * blockDim.x + threadIdx.x;
    int gwarp = t >> 5, lane = t & 31;
    int nwarps = (gridDim.x * blockDim.x) >> 5;
    alloc_ranges(g_cntN, g_offN, &g_totN, N, gwarp, nwarps, lane);
    alloc_ranges(g_cntE, g_offE, &g_totE, E, gwarp, nwarps, lane);
}

__global__ void scatter_kernel(const int* __restrict__ node, const int* __restrict__ hedge, int nnz) {
    int t = blockIdx.x * blockDim.x + threadIdx.x;
    int stride4 = gridDim.x * blockDim.x * 4;
    for (int j0 = t * 4; j0 < nnz; j0 += stride4) {
        if (j0 + 3 < nnz) {
            int4 n4 = *(const int4*)&node[j0];
            int4 h4 = *(const int4*)&hedge[j0];
            g_csrN[g_offN[n4.x] + atomicAdd(&g_curN[n4.x], 1)] = j0 + 0;
            g_csrN[g_offN[n4.y] + atomicAdd(&g_curN[n4.y], 1)] = j0 + 1;
            g_csrN[g_offN[n4.z] + atomicAdd(&g_curN[n4.z], 1)] = j0 + 2;
            g_csrN[g_offN[n4.w] + atomicAdd(&g_curN[n4.w], 1)] = j0 + 3;
            g_csrE[g_offE[h4.x] + atomicAdd(&g_curE[h4.x], 1)] = j0 + 0;
            g_csrE[g_offE[h4.y] + atomicAdd(&g_curE[h4.y], 1)] = j0 + 1;
            g_csrE[g_offE[h4.z] + atomicAdd(&g_curE[h4.z], 1)] = j0 + 2;
            g_csrE[g_offE[h4.w] + atomicAdd(&g_curE[h4.w], 1)] = j0 + 3;
        } else {
            for (int j = j0; j < nnz; j++) {
                int n = node[j], h = hedge[j];
                g_csrN[g_offN[n] + atomicAdd(&g_curN[n], 1)] = j;
                g_csrE[g_offE[h] + atomicAdd(&g_curE[h], 1)] = j;
            }
        }
    }
}

// ---------------- tiled fp32 GEMM, fp16 output (conv1 feature GEMM) ----------------
__global__ __launch_bounds__(256) void sgemm_h_kernel(const float* __restrict__ A,
                                                      const float* __restrict__ B,
                                                      __half* __restrict__ C, int M) {
    const int K = 128, NG = 256;
    __shared__ float As[16][128];
    __shared__ float Bs[16][128];
    int tid = threadIdx.x;
    int tx = tid & 15, ty = tid >> 4;
    int rowBase = blockIdx.x * 128;
    int colBase = blockIdx.y * 128;
    float acc[8][8] = {};
    for (int kt = 0; kt < K; kt += 16) {
        #pragma unroll
        for (int l = tid; l < 128 * 4; l += 256) {
            int r = l / 4, c4 = l % 4;
            int gr = rowBase + r;
            float4 v = make_float4(0.f, 0.f, 0.f, 0.f);
            if (gr < M) v = *(const float4*)&A[(size_t)gr * K + kt + c4 * 4];
            As[c4 * 4 + 0][r] = v.x;
            As[c4 * 4 + 1][r] = v.y;
            As[c4 * 4 + 2][r] = v.z;
            As[c4 * 4 + 3][r] = v.w;
        }
        #pragma unroll
        for (int l = tid; l < 16 * 32; l += 256) {
            int r = l / 32, c4 = l % 32;
            *(float4*)&Bs[r][c4 * 4] = *(const float4*)&B[(size_t)(kt + r) * NG + colBase + c4 * 4];
        }
        __syncthreads();
        #pragma unroll
        for (int k = 0; k < 16; k++) {
            float ar[8], br[8];
            #pragma unroll
            for (int i = 0; i < 8; i++) ar[i] = As[k][ty * 8 + i];
            #pragma unroll
            for (int j = 0; j < 8; j++) br[j] = Bs[k][tx * 8 + j];
            #pragma unroll
            for (int i = 0; i < 8; i++)
                #pragma unroll
                for (int j = 0; j < 8; j++) acc[i][j] += ar[i] * br[j];
        }
        __syncthreads();
    }
    #pragma unroll
    for (int i = 0; i < 8; i++) {
        int gr = rowBase + ty * 8 + i;
        if (gr < M) {
            #pragma unroll
            for (int j4 = 0; j4 < 2; j4++) {
                uint2 hv = f4_to_h4(make_float4(acc[i][j4 * 4 + 0], acc[i][j4 * 4 + 1],
                                                acc[i][j4 * 4 + 2], acc[i][j4 * 4 + 3]));
                *(uint2*)&C[(size_t)gr * NG + colBase + tx * 8 + j4 * 4] = hv;
            }
        }
    }
}

// ---------------- tiled fp32 GEMM (round-5 version, conv2) ----------------
template <int BM, int BN, int BK, int TM, int TN>
__global__ __launch_bounds__(256) void sgemm_kernel(const float* __restrict__ A,
                                                    const float* __restrict__ B,
                                                    float* __restrict__ C, int M, int N, int K) {
    constexpr int THREADS = (BM / TM) * (BN / TN);
    __shared__ float As[BK][BM];
    __shared__ float Bs[BK][BN];
    int tid = threadIdx.x;
    int tx = tid % (BN / TN);
    int ty = tid / (BN / TN);
    int rowBase = blockIdx.x * BM;
    int colBase = blockIdx.y * BN;
    float acc[TM][TN] = {};
    for (int kt = 0; kt < K; kt += BK) {
        #pragma unroll
        for (int l = tid; l < BM * BK / 4; l += THREADS) {
            int r = l / (BK / 4), c4 = l % (BK / 4);
            int gr = rowBase + r;
            float4 v = make_float4(0.f, 0.f, 0.f, 0.f);
            if (gr < M) v = *(const float4*)&A[(size_t)gr * K + kt + c4 * 4];
            As[c4 * 4 + 0][r] = v.x;
            As[c4 * 4 + 1][r] = v.y;
            As[c4 * 4 + 2][r] = v.z;
            As[c4 * 4 + 3][r] = v.w;
        }
        #pragma unroll
        for (int l = tid; l < BK * BN / 4; l += THREADS) {
            int r = l / (BN / 4), c4 = l % (BN / 4);
            *(float4*)&Bs[r][c4 * 4] = *(const float4*)&B[(size_t)(kt + r) * N + colBase + c4 * 4];
        }
        __syncthreads();
        #pragma unroll
        for (int k = 0; k < BK; k++) {
            float ar[TM], br[TN];
            #pragma unroll
            for (int i = 0; i < TM; i++) ar[i] = As[k][ty * TM + i];
            #pragma unroll
            for (int j = 0; j < TN; j++) br[j] = Bs[k][tx * TN + j];
            #pragma unroll
            for (int i = 0; i < TM; i++)
                #pragma unroll
                for (int j = 0; j < TN; j++) acc[i][j] += ar[i] * br[j];
        }
        __syncthreads();
    }
    #pragma unroll
    for (int i = 0; i < TM; i++) {
        int gr = rowBase + ty * TM + i;
        if (gr < M) {
            #pragma unroll
            for (int j4 = 0; j4 < TN / 4; j4++) {
                float4 v = make_float4(acc[i][j4 * 4 + 0], acc[i][j4 * 4 + 1],
                                       acc[i][j4 * 4 + 2], acc[i][j4 * 4 + 3]);
                *(float4*)&C[(size_t)gr * N + colBase + tx * TN + j4 * 4] = v;
            }
        }
    }
}

// ---------------- fold att into W1 ----------------
__global__ void attmat_kernel(const float* __restrict__ W1, const float* __restrict__ att) {
    int t = threadIdx.x;           // 512 threads
    int k = t >> 2, h = t & 3;
    const float* wrow = &W1[k * 256 + h * 64];
    const float* a1 = &att[h * 128];
    const float* a2 = &att[h * 128 + 64];
    float s1 = 0.f, s2 = 0.f;
    #pragma unroll
    for (int f = 0; f < 64; f++) {
        float w = wrow[f];
        s1 += w * a1[f];
        s2 += w * a2[f];
    }
    g_A1[k * 4 + h] = s1;
    g_A2[k * 4 + h] = s2;
}

// ---------------- attention logits: ax = x @ A1, ae = hat @ A2 ----------------
__global__ __launch_bounds__(256) void axae_kernel(const float* __restrict__ x,
                                                   const float* __restrict__ hat, int N, int E) {
    __shared__ float sA1[128 * 4], sA2[128 * 4];
    int tid = threadIdx.x;
    for (int i = tid; i < 512; i += 256) { sA1[i] = g_A1[i]; sA2[i] = g_A2[i]; }
    __syncthreads();
    int r = blockIdx.x * 256 + tid;
    if (r >= N + E) return;
    bool isNode = r < N;
    const float4* row = (const float4*)(isNode ? &x[(size_t)r * 128] : &hat[(size_t)(r - N) * 128]);
    const float* Am = isNode ? sA1 : sA2;
    float acc0 = 0.f, acc1 = 0.f, acc2 = 0.f, acc3 = 0.f;
    #pragma unroll
    for (int k4 = 0; k4 < 32; k4++) {
        float4 v = row[k4];
        const float* a = &Am[k4 * 16];
        acc0 += v.x * a[0];  acc1 += v.x * a[1];  acc2 += v.x * a[2];  acc3 += v.x * a[3];
        acc0 += v.y * a[4];  acc1 += v.y * a[5];  acc2 += v.y * a[6];  acc3 += v.y * a[7];
        acc0 += v.z * a[8];  acc1 += v.z * a[9];  acc2 += v.z * a[10]; acc3 += v.z * a[11];
        acc0 += v.w * a[12]; acc1 += v.w * a[13]; acc2 += v.w * a[14]; acc3 += v.w * a[15];
    }
    float* dst = isNode ? &g_ax[r * 4] : &g_ae[(r - N) * 4];
    dst[0] = acc0; dst[1] = acc1; dst[2] = acc2; dst[3] = acc3;
}

// ---------------- conv1 edge stage: segment softmax + propagate 1 (fp16 gather) ----------------
#define ECAP 1024
__global__ __launch_bounds__(256) void edge1_kernel(const int* __restrict__ nodeIdx) {
    int e = blockIdx.x;
    int tid = threadIdx.x;
    int lane = tid & 31, warp = tid >> 5;
    int beg = g_offE[e];
    int k = g_cntE[e];
    float aeh[4];
    #pragma unroll
    for (int h = 0; h < 4; h++) aeh[h] = g_ae[e * 4 + h];

    __shared__ int snode[ECAP];
    __shared__ int sidx[ECAP];
    __shared__ float slog[ECAP * 4];
    __shared__ float4 racc[256];
    __shared__ float wr[8][4];
    __shared__ float smax[4], sinv[4];

    int g = tid >> 6, f4 = tid & 63, hh = f4 >> 4;
    float Binv = k > 0 ? 1.f / (float)k : 0.f;
    float4 acc = make_float4(0.f, 0.f, 0.f, 0.f);
    const uint2* xh4 = (const uint2*)g_xh_h;   // 4 halves per uint2, 64 per row

    if (k <= ECAP) {
        float lmax[4] = {-1e30f, -1e30f, -1e30f, -1e30f};
        for (int j = tid; j < k; j += 256) {
            int i = g_csrE[beg + j];
            int n = nodeIdx[i];
            sidx[j] = i;
            snode[j] = n;
            #pragma unroll
            for (int h = 0; h < 4; h++) {
                float z = g_ax[n * 4 + h] + aeh[h];
                z = z > 0.f ? z : 0.2f * z;
                slog[j * 4 + h] = z;
                lmax[h] = fmaxf(lmax[h], z);
            }
        }
        #pragma unroll
        for (int o = 16; o; o >>= 1)
            #pragma unroll
            for (int h = 0; h < 4; h++)
                lmax[h] = fmaxf(lmax[h], __shfl_xor_sync(0xffffffffu, lmax[h], o));
        if (lane == 0)
            #pragma unroll
            for (int h = 0; h < 4; h++) wr[warp][h] = lmax[h];
        __syncthreads();
        if (tid < 4) {
            float r = wr[0][tid];
            #pragma unroll
            for (int w2 = 1; w2 < 8; w2++) r = fmaxf(r, wr[w2][tid]);
            smax[tid] = r;
        }
        __syncthreads();

        float lsum[4] = {0.f, 0.f, 0.f, 0.f};
        for (int j = tid; j < k; j += 256) {
            #pragma unroll
            for (int h = 0; h < 4; h++) {
                float ex = __expf(slog[j * 4 + h] - smax[h]);
                slog[j * 4 + h] = ex;
                lsum[h] += ex;
            }
        }
        #pragma unroll
        for (int o = 16; o; o >>= 1)
            #pragma unroll
            for (int h = 0; h < 4; h++) lsum[h] += __shfl_xor_sync(0xffffffffu, lsum[h], o);
        if (lane == 0)
            #pragma unroll
            for (int h = 0; h < 4; h++) wr[warp][h] = lsum[h];
        __syncthreads();
        if (tid < 4) {
            float r = wr[0][tid];
            #pragma unroll
            for (int w2 = 1; w2 < 8; w2++) r += wr[w2][tid];
            sinv[tid] = 1.f / (r + 1e-16f);
        }
        __syncthreads();

        for (int j = tid; j < k; j += 256) {
            float4 a;
            a.x = slog[j * 4 + 0] * sinv[0];
            a.y = slog[j * 4 + 1] * sinv[1];
            a.z = slog[j * 4 + 2] * sinv[2];
            a.w = slog[j * 4 + 3] * sinv[3];
            slog[j * 4 + 0] = a.x; slog[j * 4 + 1] = a.y;
            slog[j * 4 + 2] = a.z; slog[j * 4 + 3] = a.w;
            ((float4*)g_alpha)[sidx[j]] = a;
        }
        __syncthreads();

        for (int j = g; j < k; j += 4) {
            float a = slog[j * 4 + hh];
            float4 xv = h4_to_f4(xh4[(size_t)snode[j] * 64 + f4]);
            acc.x += a * xv.x; acc.y += a * xv.y; acc.z += a * xv.z; acc.w += a * xv.w;
        }
    } else {
        float lmax[4] = {-1e30f, -1e30f, -1e30f, -1e30f};
        for (int j = tid; j < k; j += 256) {
            int i = g_csrE[beg + j];
            int n = nodeIdx[i];
            #pragma unroll
            for (int h = 0; h < 4; h++) {
                float z = g_ax[n * 4 + h] + aeh[h];
                z = z > 0.f ? z : 0.2f * z;
                g_alpha[i * 4 + h] = z;
                lmax[h] = fmaxf(lmax[h], z);
            }
        }
        #pragma unroll
        for (int o = 16; o; o >>= 1)
            #pragma unroll
            for (int h = 0; h < 4; h++)
                lmax[h] = fmaxf(lmax[h], __shfl_xor_sync(0xffffffffu, lmax[h], o));
        if (lane == 0)
            #pragma unroll
            for (int h = 0; h < 4; h++) wr[warp][h] = lmax[h];
        __syncthreads();
        if (tid < 4) {
            float r = wr[0][tid];
            #pragma unroll
            for (int w2 = 1; w2 < 8; w2++) r = fmaxf(r, wr[w2][tid]);
            smax[tid] = r;
        }
        __syncthreads();
        float lsum[4] = {0.f, 0.f, 0.f, 0.f};
        for (int j = tid; j < k; j += 256) {
            int i = g_csrE[beg + j];
            #pragma unroll
            for (int h = 0; h < 4; h++) {
                float ex = __expf(g_alpha[i * 4 + h] - smax[h]);
                g_alpha[i * 4 + h] = ex;
                lsum[h] += ex;
            }
        }
        #pragma unroll
        for (int o = 16; o; o >>= 1)
            #pragma unroll
            for (int h = 0; h < 4; h++) lsum[h] += __shfl_xor_sync(0xffffffffu, lsum[h], o);
        if (lane == 0)
            #pragma unroll
            for (int h = 0; h < 4; h++) wr[warp][h] = lsum[h];
        __syncthreads();
        if (tid < 4) {
            float r = wr[0][tid];
            #pragma unroll
            for (int w2 = 1; w2 < 8; w2++) r += wr[w2][tid];
            sinv[tid] = 1.f / (r + 1e-16f);
        }
        __syncthreads();
        for (int j = tid; j < k; j += 256) {
            int i = g_csrE[beg + j];
            #pragma unroll
            for (int h = 0; h < 4; h++) g_alpha[i * 4 + h] *= sinv[h];
        }
        __syncthreads();
        for (int base = 0; base < k; base += ECAP) {
            int c = min(ECAP, k - base);
            __syncthreads();
            for (int j = tid; j < c; j += 256) {
                int i = g_csrE[beg + base + j];
                snode[j] = nodeIdx[i];
                ((float4*)slog)[j] = ((const float4*)g_alpha)[i];
            }
            __syncthreads();
            for (int j = g; j < c; j += 4) {
                float a = slog[j * 4 + hh];
                float4 xv = h4_to_f4(xh4[(size_t)snode[j] * 64 + f4]);
                acc.x += a * xv.x; acc.y += a * xv.y; acc.z += a * xv.z; acc.w += a * xv.w;
            }
        }
    }

    racc[tid] = acc;
    __syncthreads();
    if (tid < 64) {
        float4 a = racc[tid], b = racc[tid + 64], c2 = racc[tid + 128], d2 = racc[tid + 192];
        float4 r;
        r.x = (a.x + b.x + c2.x + d2.x) * Binv;
        r.y = (a.y + b.y + c2.y + d2.y) * Binv;
        r.z = (a.z + b.z + c2.z + d2.z) * Binv;
        r.w = (a.w + b.w + c2.w + d2.w) * Binv;
        ((uint2*)g_eh_h)[e * 64 + tid] = f4_to_h4(r);
    }
}

__device__ __forceinline__ float eluf(float x) { return x > 0.f ? x : expm1f(x); }

// ---------------- conv1 node stage (fp16 eh gather) ----------------
__global__ __launch_bounds__(256) void node1_kernel(const int* __restrict__ hedgeIdx,
                                                    const float* __restrict__ b1) {
    int n = blockIdx.x;
    int tid = threadIdx.x;
    int beg = g_offN[n];
    int d = g_cntN[n];
    int end = beg + d;
    float Dinv = d > 0 ? 1.f / (float)d : 0.f;
    int g = tid >> 6, f4 = tid & 63, h = f4 >> 4;
    float4 acc = make_float4(0.f, 0.f, 0.f, 0.f);
    const uint2* eh4 = (const uint2*)g_eh_h;
    for (int j = beg + g; j < end; j += 4) {
        int i = g_csrN[j];
        int e = hedgeIdx[i];
        float a = g_alpha[i * 4 + h];
        float4 ev = h4_to_f4(eh4[(size_t)e * 64 + f4]);
        acc.x += a * ev.x; acc.y += a * ev.y; acc.z += a * ev.z; acc.w += a * ev.w;
    }
    __shared__ float4 racc[256];
    racc[tid] = acc;
    __syncthreads();
    if (tid < 64) {
        float4 a = racc[tid], b = racc[tid + 64], c2 = racc[tid + 128], d2 = racc[tid + 192];
        float4 bv = ((const float4*)b1)[tid];
        float4 r;
        r.x = eluf((a.x + b.x + c2.x + d2.x) * Dinv + bv.x);
        r.y = eluf((a.y + b.y + c2.y + d2.y) * Dinv + bv.y);
        r.z = eluf((a.z + b.z + c2.z + d2.z) * Dinv + bv.z);
        r.w = eluf((a.w + b.w + c2.w + d2.w) * Dinv + bv.w);
        ((float4*)g_h)[n * 64 + tid] = r;
    }
}

// ---------------- conv2 ----------------
__global__ __launch_bounds__(256) void edge2_kernel(const int* __restrict__ nodeIdx) {
    int e = blockIdx.x;
    int tid = threadIdx.x;
    int beg = g_offE[e];
    int k = g_cntE[e];
    int end = beg + k;
    float Binv = k > 0 ? 1.f / (float)k : 0.f;
    int g = tid >> 6, f = tid & 63;
    float acc = 0.f;
    for (int j = beg + g; j < end; j += 4) {
        int i = g_csrE[j];
        int n = nodeIdx[i];
        acc += g_xh2[(size_t)n * 64 + f];
    }
    __shared__ float racc[256];
    racc[tid] = acc;
    __syncthreads();
    if (tid < 64)
        g_eh2[e * 64 + tid] = (racc[tid] + racc[tid + 64] + racc[tid + 128] + racc[tid + 192]) * Binv;
}

__global__ __launch_bounds__(256) void node2_kernel(const int* __restrict__ hedgeIdx,
                                                    const float* __restrict__ b2,
                                                    float* __restrict__ out, int N) {
    int warp = threadIdx.x >> 5, lane = threadIdx.x & 31;
    int n = blockIdx.x * 8 + warp;
    if (n >= N) return;
    int beg = g_offN[n];
    int d = g_cntN[n];
    float Dinv = d > 0 ? 1.f / (float)d : 0.f;
    const float2* eh2 = (const float2*)g_eh2;
    float ax = 0.f, ay = 0.f;
    int j = beg, end = beg + d;
    for (; j + 1 < end; j += 2) {
        int i0 = g_csrN[j], i1 = g_csrN[j + 1];
        int e0 = hedgeIdx[i0], e1 = hedgeIdx[i1];
        float2 v0 = eh2[e0 * 32 + lane];
        float2 v1 = eh2[e1 * 32 + lane];
        ax += v0.x + v1.x; ay += v0.y + v1.y;
    }
    if (j < end) {
        int i = g_csrN[j];
        int e = hedgeIdx[i];
        float2 v = eh2[e * 32 + lane];
        ax += v.x; ay += v.y;
    }
    float2 bb = ((const float2*)b2)[lane];
    ((float2*)out)[(size_t)n * 32 + lane] = make_float2(ax * Dinv + bb.x, ay * Dinv + bb.y);
}

// ---------------- launch (exact R8 fork structure) ----------------
extern "C" void kernel_launch(void* const* d_in, const int* in_sizes, int n_in,
                              void* d_out, int out_size) {
    const float* x    = (const float*)d_in[0];
    const int*   ei   = (const int*)d_in[1];
    const float* hat  = (const float*)d_in[2];
    const float* W1   = (const float*)d_in[3];
    const float* att1 = (const float*)d_in[4];
    const float* b1   = (const float*)d_in[5];
    const float* W2   = (const float*)d_in[6];
    const float* b2   = (const float*)d_in[7];
    float* out = (float*)d_out;

    int N   = in_sizes[0] / 128;
    int NNZ = in_sizes[1] / 2;
    int E   = in_sizes[2] / 128;
    const int* node  = ei;
    const int* hedge = ei + NNZ;

    float *p_h, *p_xh2;
    __half* p_xh_h;
    cudaGetSymbolAddress((void**)&p_h, g_h);
    cudaGetSymbolAddress((void**)&p_xh2, g_xh2);
    cudaGetSymbolAddress((void**)&p_xh_h, g_xh_h);

    // lazy one-time side stream + events (host objects only)
    static cudaStream_t s1 = nullptr;
    static cudaEvent_t evFork = nullptr, evJoin = nullptr;
    if (s1 == nullptr) {
        cudaStreamCreateWithFlags(&s1, cudaStreamNonBlocking);
        cudaEventCreateWithFlags(&evFork, cudaEventDisableTiming);
        cudaEventCreateWithFlags(&evJoin, cudaEventDisableTiming);
    }

    // fork: side stream runs GEMM + attention-logit chain; main runs CSR build (R8 winner)
    cudaEventRecord(evFork, 0);
    cudaStreamWaitEvent(s1, evFork, 0);

    // side stream (chain B)
    sgemm_h_kernel<<<dim3((N + 127) / 128, 2), 256, 0, s1>>>(x, W1, p_xh_h, N);
    attmat_kernel<<<1, 512, 0, s1>>>(W1, att1);
    axae_kernel<<<(N + E + 255) / 256, 256, 0, s1>>>(x, hat, N, E);
    cudaEventRecord(evJoin, s1);

    // main stream (chain A): CSR build
    zero_counts_kernel<<<128, 256>>>(N, E);
    count_kernel<<<480, 256>>>(node, hedge, NNZ);
    alloc_kernel<<<64, 256>>>(N, E);
    scatter_kernel<<<480, 256>>>(node, hedge, NNZ);

    // join
    cudaStreamWaitEvent(0, evJoin, 0);

    // conv1: softmax + propagate 1 + node stage
    edge1_kernel<<<E, 256>>>(node);
    node1_kernel<<<N, 256>>>(hedge, b1);

    // conv2
    sgemm_kernel<128, 64, 16, 8, 4><<<dim3((N + 127) / 128, 1), 256>>>(p_h, W2, p_xh2, N, 64, 256);
    edge2_kernel<<<E, 256>>>(node);
    node2_kernel<<<(N + 7) / 8, 256>>>(hedge, b2, out, N);
}

// round 13
// speedup vs baseline: 1.4671x; 1.0510x over previous
#include <cuda_runtime.h>
#include <cuda_fp16.h>
#include <math.h>
#include <cstdint>

#define MAXN   50000
#define MAXE   10000
#define MAXNNZ 600000

// ---------------- scratch (static __device__, no allocations) ----------------
__device__ __half g_xh_h[MAXN * 256];  // x @ W1 (fp16 storage, consumed by edge1)
__device__ __half g_eh_h[MAXE * 256];  // propagate-1 out (fp16, consumed by node1)
__device__ __half g_xh2_h[MAXN * 64];  // h @ W2 (fp16, consumed by edge2)
__device__ __half g_eh2_h[MAXE * 64];  // conv2 edge out (fp16, consumed by node2)
__device__ float g_ax[MAXN * 4];
__device__ float g_ae[MAXE * 4];
__device__ float g_A1[128 * 4];
__device__ float g_A2[128 * 4];
__device__ float g_alpha[MAXNNZ * 4];
__device__ float g_h[MAXN * 256];
__device__ int g_cntN[MAXN], g_cntE[MAXE];
__device__ int g_curN[MAXN], g_curE[MAXE];
__device__ int g_offN[MAXN], g_offE[MAXE];
__device__ int g_csrN[MAXNNZ], g_csrE[MAXNNZ];
__device__ int g_totN, g_totE;

__device__ __forceinline__ float4 h4_to_f4(uint2 raw) {
    __half2 h0 = *(__half2*)&raw.x;
    __half2 h1 = *(__half2*)&raw.y;
    float2 a = __half22float2(h0), b = __half22float2(h1);
    return make_float4(a.x, a.y, b.x, b.y);
}
__device__ __forceinline__ uint2 f4_to_h4(float4 v) {
    __half2 h0 = __floats2half2_rn(v.x, v.y);
    __half2 h1 = __floats2half2_rn(v.z, v.w);
    uint2 r;
    r.x = *(uint32_t*)&h0;
    r.y = *(uint32_t*)&h1;
    return r;
}

// ---------------- fp16 HMMA GEMM: xh = x @ W1 (fp32 accumulate, fp16 out) ----------------
__device__ __forceinline__ void mma_f16(float* c, const uint32_t* a, const uint32_t* b) {
    asm volatile(
        "mma.sync.aligned.m16n8k16.row.col.f32.f16.f16.f32 "
        "{%0,%1,%2,%3}, {%4,%5,%6,%7}, {%8,%9}, {%0,%1,%2,%3};"
        : "+f"(c[0]), "+f"(c[1]), "+f"(c[2]), "+f"(c[3])
        : "r"(a[0]), "r"(a[1]), "r"(a[2]), "r"(a[3]), "r"(b[0]), "r"(b[1]));
}

// BM=BN=128, BK=32, 8 warps (2x4), warp tile 64x32, MT=NT=4.
__global__ __launch_bounds__(256) void hmma_gemm_kernel(const float* __restrict__ A,
                                                        const float* __restrict__ B,
                                                        __half* __restrict__ C, int M) {
    const int K = 128, NG = 256;
    __shared__ uint32_t AsU[128 * 18];   // [row][18 uint] = 16 data half2 + pad
    __shared__ uint32_t BsU[128 * 18];   // [n][18 uint], Bs[n][k] halves
    __half* Bs_h = (__half*)BsU;
    int tid = threadIdx.x, lane = tid & 31, wid = tid >> 5;
    int gid = lane >> 2, tig = lane & 3;
    int warpM = wid >> 2, warpN = wid & 3;
    int rowBase = blockIdx.x * 128, colBase = blockIdx.y * 128;
    float acc[4][4][4] = {};

    for (int kt = 0; kt < K; kt += 32) {
        // A tile [128 rows][32 k] -> half, row-major
        #pragma unroll
        for (int u = 0; u < 4; u++) {
            int l = tid + u * 256;
            int r = l >> 3, c4 = l & 7;
            int gr = rowBase + r;
            float4 v = make_float4(0.f, 0.f, 0.f, 0.f);
            if (gr < M) v = *(const float4*)&A[(size_t)gr * K + kt + c4 * 4];
            __half2 h01 = __floats2half2_rn(v.x, v.y);
            __half2 h23 = __floats2half2_rn(v.z, v.w);
            AsU[r * 18 + c4 * 2 + 0] = *(uint32_t*)&h01;
            AsU[r * 18 + c4 * 2 + 1] = *(uint32_t*)&h23;
        }
        // B tile: Bs[n][k] = W1[kt+k][colBase+n] (transpose during load)
        #pragma unroll
        for (int u = 0; u < 4; u++) {
            int l = tid + u * 256;
            int k = l >> 5, n4 = l & 31;
            float4 v = *(const float4*)&B[(size_t)(kt + k) * NG + colBase + n4 * 4];
            Bs_h[(n4 * 4 + 0) * 36 + k] = __float2half(v.x);
            Bs_h[(n4 * 4 + 1) * 36 + k] = __float2half(v.y);
            Bs_h[(n4 * 4 + 2) * 36 + k] = __float2half(v.z);
            Bs_h[(n4 * 4 + 3) * 36 + k] = __float2half(v.w);
        }
        __syncthreads();
        #pragma unroll
        for (int s = 0; s < 2; s++) {
            uint32_t af[4][4], bf[4][2];
            #pragma unroll
            for (int mt = 0; mt < 4; mt++) {
                int r = warpM * 64 + mt * 16 + gid;
                af[mt][0] = AsU[r * 18 + s * 8 + tig];
                af[mt][1] = AsU[(r + 8) * 18 + s * 8 + tig];
                af[mt][2] = AsU[r * 18 + s * 8 + tig + 4];
                af[mt][3] = AsU[(r + 8) * 18 + s * 8 + tig + 4];
            }
            #pragma unroll
            for (int nt = 0; nt < 4; nt++) {
                int n = warpN * 32 + nt * 8 + gid;
                bf[nt][0] = BsU[n * 18 + s * 8 + tig];
                bf[nt][1] = BsU[n * 18 + s * 8 + tig + 4];
            }
            #pragma unroll
            for (int mt = 0; mt < 4; mt++)
                #pragma unroll
                for (int nt = 0; nt < 4; nt++) mma_f16(acc[mt][nt], af[mt], bf[nt]);
        }
        __syncthreads();
    }

    #pragma unroll
    for (int mt = 0; mt < 4; mt++) {
        int r0 = rowBase + warpM * 64 + mt * 16 + gid;
        #pragma unroll
        for (int nt = 0; nt < 4; nt++) {
            int c = colBase + warpN * 32 + nt * 8 + tig * 2;
            if (r0 < M) {
                __half2 h = __floats2half2_rn(acc[mt][nt][0], acc[mt][nt][1]);
                *(uint32_t*)&C[(size_t)r0 * NG + c] = *(uint32_t*)&h;
            }
            if (r0 + 8 < M) {
                __half2 h = __floats2half2_rn(acc[mt][nt][2], acc[mt][nt][3]);
                *(uint32_t*)&C[(size_t)(r0 + 8) * NG + c] = *(uint32_t*)&h;
            }
        }
    }
}

// ---------------- CSR construction ----------------
__global__ void zero_counts_kernel(int N, int E) {
    int i = blockIdx.x * blockDim.x + threadIdx.x;
    int s = gridDim.x * blockDim.x;
    if (i == 0) { g_totN = 0; g_totE = 0; }
    for (int j = i; j < N; j += s) { g_cntN[j] = 0; g_curN[j] = 0; }
    for (int j = i; j < E; j += s) { g_cntE[j] = 0; g_curE[j] = 0; }
}

__global__ void count_kernel(const int* __restrict__ node, const int* __restrict__ hedge, int nnz) {
    int t = blockIdx.x * blockDim.x + threadIdx.x;
    int stride4 = gridDim.x * blockDim.x * 4;
    for (int j0 = t * 4; j0 < nnz; j0 += stride4) {
        if (j0 + 3 < nnz) {
            int4 n4 = *(const int4*)&node[j0];
            int4 h4 = *(const int4*)&hedge[j0];
            atomicAdd(&g_cntN[n4.x], 1); atomicAdd(&g_cntN[n4.y], 1);
            atomicAdd(&g_cntN[n4.z], 1); atomicAdd(&g_cntN[n4.w], 1);
            atomicAdd(&g_cntE[h4.x], 1); atomicAdd(&g_cntE[h4.y], 1);
            atomicAdd(&g_cntE[h4.z], 1); atomicAdd(&g_cntE[h4.w], 1);
        } else {
            for (int j = j0; j < nnz; j++) {
                atomicAdd(&g_cntN[node[j]], 1);
                atomicAdd(&g_cntE[hedge[j]], 1);
            }
        }
    }
}

__device__ __forceinline__ void alloc_ranges(const int* __restrict__ cnt, int* __restrict__ off,
                                             int* total, int n, int gwarp, int nwarps, int lane) {
    for (int j0 = gwarp * 32; j0 < n; j0 += nwarps * 32) {
        int j = j0 + lane;
        int c = (j < n) ? cnt[j] : 0;
        int x = c;
        #pragma unroll
        for (int o = 1; o < 32; o <<= 1) {
            int y = __shfl_up_sync(0xffffffffu, x, o);
            if (lane >= o) x += y;
        }
        int wtot = __shfl_sync(0xffffffffu, x, 31);
        int base = 0;
        if (lane == 0) base = atomicAdd(total, wtot);
        base = __shfl_sync(0xffffffffu, base, 0);
        if (j < n) off[j] = base + x - c;
    }
}

__global__ void alloc_kernel(int N, int E) {
    int t = blockIdx.x * blockDim.x + threadIdx.x;
    int gwarp = t >> 5, lane = t & 31;
    int nwarps = (gridDim.x * blockDim.x) >> 5;
    alloc_ranges(g_cntN, g_offN, &g_totN, N, gwarp, nwarps, lane);
    alloc_ranges(g_cntE, g_offE, &g_totE, E, gwarp, nwarps, lane);
}

__global__ void scatter_kernel(const int* __restrict__ node, const int* __restrict__ hedge, int nnz) {
    int t = blockIdx.x * blockDim.x + threadIdx.x;
    int stride4 = gridDim.x * blockDim.x * 4;
    for (int j0 = t * 4; j0 < nnz; j0 += stride4) {
        if (j0 + 3 < nnz) {
            int4 n4 = *(const int4*)&node[j0];
            int4 h4 = *(const int4*)&hedge[j0];
            g_csrN[g_offN[n4.x] + atomicAdd(&g_curN[n4.x], 1)] = j0 + 0;
            g_csrN[g_offN[n4.y] + atomicAdd(&g_curN[n4.y], 1)] = j0 + 1;
            g_csrN[g_offN[n4.z] + atomicAdd(&g_curN[n4.z], 1)] = j0 + 2;
            g_csrN[g_offN[n4.w] + atomicAdd(&g_curN[n4.w], 1)] = j0 + 3;
            g_csrE[g_offE[h4.x] + atomicAdd(&g_curE[h4.x], 1)] = j0 + 0;
            g_csrE[g_offE[h4.y] + atomicAdd(&g_curE[h4.y], 1)] = j0 + 1;
            g_csrE[g_offE[h4.z] + atomicAdd(&g_curE[h4.z], 1)] = j0 + 2;
            g_csrE[g_offE[h4.w] + atomicAdd(&g_curE[h4.w], 1)] = j0 + 3;
        } else {
            for (int j = j0; j < nnz; j++) {
                int n = node[j], h = hedge[j];
                g_csrN[g_offN[n] + atomicAdd(&g_curN[n], 1)] = j;
                g_csrE[g_offE[h] + atomicAdd(&g_curE[h], 1)] = j;
            }
        }
    }
}

// ---------------- tiled fp32 GEMM with fp16 output (conv2: h @ W2) ----------------
template <int BM, int BN, int BK, int TM, int TN>
__global__ __launch_bounds__(256) void sgemm_h_out_kernel(const float* __restrict__ A,
                                                          const float* __restrict__ B,
                                                          __half* __restrict__ C, int M, int N, int K) {
    constexpr int THREADS = (BM / TM) * (BN / TN);
    __shared__ float As[BK][BM];
    __shared__ float Bs[BK][BN];
    int tid = threadIdx.x;
    int tx = tid % (BN / TN);
    int ty = tid / (BN / TN);
    int rowBase = blockIdx.x * BM;
    int colBase = blockIdx.y * BN;
    float acc[TM][TN] = {};
    for (int kt = 0; kt < K; kt += BK) {
        #pragma unroll
        for (int l = tid; l < BM * BK / 4; l += THREADS) {
            int r = l / (BK / 4), c4 = l % (BK / 4);
            int gr = rowBase + r;
            float4 v = make_float4(0.f, 0.f, 0.f, 0.f);
            if (gr < M) v = *(const float4*)&A[(size_t)gr * K + kt + c4 * 4];
            As[c4 * 4 + 0][r] = v.x;
            As[c4 * 4 + 1][r] = v.y;
            As[c4 * 4 + 2][r] = v.z;
            As[c4 * 4 + 3][r] = v.w;
        }
        #pragma unroll
        for (int l = tid; l < BK * BN / 4; l += THREADS) {
            int r = l / (BN / 4), c4 = l % (BN / 4);
            *(float4*)&Bs[r][c4 * 4] = *(const float4*)&B[(size_t)(kt + r) * N + colBase + c4 * 4];
        }
        __syncthreads();
        #pragma unroll
        for (int k = 0; k < BK; k++) {
            float ar[TM], br[TN];
            #pragma unroll
            for (int i = 0; i < TM; i++) ar[i] = As[k][ty * TM + i];
            #pragma unroll
            for (int j = 0; j < TN; j++) br[j] = Bs[k][tx * TN + j];
            #pragma unroll
            for (int i = 0; i < TM; i++)
                #pragma unroll
                for (int j = 0; j < TN; j++) acc[i][j] += ar[i] * br[j];
        }
        __syncthreads();
    }
    #pragma unroll
    for (int i = 0; i < TM; i++) {
        int gr = rowBase + ty * TM + i;
        if (gr < M) {
            #pragma unroll
            for (int j2 = 0; j2 < TN / 2; j2++) {
                __half2 h = __floats2half2_rn(acc[i][j2 * 2 + 0], acc[i][j2 * 2 + 1]);
                *(uint32_t*)&C[(size_t)gr * N + colBase + tx * TN + j2 * 2] = *(uint32_t*)&h;
            }
        }
    }
}

// ---------------- fold att into W1 ----------------
__global__ void attmat_kernel(const float* __restrict__ W1, const float* __restrict__ att) {
    int t = threadIdx.x;           // 512 threads
    int k = t >> 2, h = t & 3;
    const float* wrow = &W1[k * 256 + h * 64];
    const float* a1 = &att[h * 128];
    const float* a2 = &att[h * 128 + 64];
    float s1 = 0.f, s2 = 0.f;
    #pragma unroll
    for (int f = 0; f < 64; f++) {
        float w = wrow[f];
        s1 += w * a1[f];
        s2 += w * a2[f];
    }
    g_A1[k * 4 + h] = s1;
    g_A2[k * 4 + h] = s2;
}

// ---------------- attention logits ----------------
__global__ __launch_bounds__(256) void axae_kernel(const float* __restrict__ x,
                                                   const float* __restrict__ hat, int N, int E) {
    __shared__ float sA1[128 * 4], sA2[128 * 4];
    int tid = threadIdx.x;
    for (int i = tid; i < 512; i += 256) { sA1[i] = g_A1[i]; sA2[i] = g_A2[i]; }
    __syncthreads();
    int r = blockIdx.x * 256 + tid;
    if (r >= N + E) return;
    bool isNode = r < N;
    const float4* row = (const float4*)(isNode ? &x[(size_t)r * 128] : &hat[(size_t)(r - N) * 128]);
    const float* Am = isNode ? sA1 : sA2;
    float acc0 = 0.f, acc1 = 0.f, acc2 = 0.f, acc3 = 0.f;
    #pragma unroll
    for (int k4 = 0; k4 < 32; k4++) {
        float4 v = row[k4];
        const float* a = &Am[k4 * 16];
        acc0 += v.x * a[0];  acc1 += v.x * a[1];  acc2 += v.x * a[2];  acc3 += v.x * a[3];
        acc0 += v.y * a[4];  acc1 += v.y * a[5];  acc2 += v.y * a[6];  acc3 += v.y * a[7];
        acc0 += v.z * a[8];  acc1 += v.z * a[9];  acc2 += v.z * a[10]; acc3 += v.z * a[11];
        acc0 += v.w * a[12]; acc1 += v.w * a[13]; acc2 += v.w * a[14]; acc3 += v.w * a[15];
    }
    float* dst = isNode ? &g_ax[r * 4] : &g_ae[(r - N) * 4];
    dst[0] = acc0; dst[1] = acc1; dst[2] = acc2; dst[3] = acc3;
}

// ---------------- conv1 edge stage: segment softmax + propagate 1 (fp16 gather) ----------------
#define ECAP 1024
__global__ __launch_bounds__(256) void edge1_kernel(const int* __restrict__ nodeIdx) {
    int e = blockIdx.x;
    int tid = threadIdx.x;
    int lane = tid & 31, warp = tid >> 5;
    int beg = g_offE[e];
    int k = g_cntE[e];
    float aeh[4];
    #pragma unroll
    for (int h = 0; h < 4; h++) aeh[h] = g_ae[e * 4 + h];

    __shared__ int snode[ECAP];
    __shared__ int sidx[ECAP];
    __shared__ float slog[ECAP * 4];
    __shared__ float4 racc[256];
    __shared__ float wr[8][4];
    __shared__ float smax[4], sinv[4];

    int g = tid >> 6, f4 = tid & 63, hh = f4 >> 4;
    float Binv = k > 0 ? 1.f / (float)k : 0.f;
    float4 acc = make_float4(0.f, 0.f, 0.f, 0.f);
    const uint2* xh4 = (const uint2*)g_xh_h;

    if (k <= ECAP) {
        float lmax[4] = {-1e30f, -1e30f, -1e30f, -1e30f};
        for (int j = tid; j < k; j += 256) {
            int i = g_csrE[beg + j];
            int n = nodeIdx[i];
            sidx[j] = i;
            snode[j] = n;
            #pragma unroll
            for (int h = 0; h < 4; h++) {
                float z = g_ax[n * 4 + h] + aeh[h];
                z = z > 0.f ? z : 0.2f * z;
                slog[j * 4 + h] = z;
                lmax[h] = fmaxf(lmax[h], z);
            }
        }
        #pragma unroll
        for (int o = 16; o; o >>= 1)
            #pragma unroll
            for (int h = 0; h < 4; h++)
                lmax[h] = fmaxf(lmax[h], __shfl_xor_sync(0xffffffffu, lmax[h], o));
        if (lane == 0)
            #pragma unroll
            for (int h = 0; h < 4; h++) wr[warp][h] = lmax[h];
        __syncthreads();
        if (tid < 4) {
            float r = wr[0][tid];
            #pragma unroll
            for (int w2 = 1; w2 < 8; w2++) r = fmaxf(r, wr[w2][tid]);
            smax[tid] = r;
        }
        __syncthreads();

        float lsum[4] = {0.f, 0.f, 0.f, 0.f};
        for (int j = tid; j < k; j += 256) {
            #pragma unroll
            for (int h = 0; h < 4; h++) {
                float ex = __expf(slog[j * 4 + h] - smax[h]);
                slog[j * 4 + h] = ex;
                lsum[h] += ex;
            }
        }
        #pragma unroll
        for (int o = 16; o; o >>= 1)
            #pragma unroll
            for (int h = 0; h < 4; h++) lsum[h] += __shfl_xor_sync(0xffffffffu, lsum[h], o);
        if (lane == 0)
            #pragma unroll
            for (int h = 0; h < 4; h++) wr[warp][h] = lsum[h];
        __syncthreads();
        if (tid < 4) {
            float r = wr[0][tid];
            #pragma unroll
            for (int w2 = 1; w2 < 8; w2++) r += wr[w2][tid];
            sinv[tid] = 1.f / (r + 1e-16f);
        }
        __syncthreads();

        for (int j = tid; j < k; j += 256) {
            float4 a;
            a.x = slog[j * 4 + 0] * sinv[0];
            a.y = slog[j * 4 + 1] * sinv[1];
            a.z = slog[j * 4 + 2] * sinv[2];
            a.w = slog[j * 4 + 3] * sinv[3];
            slog[j * 4 + 0] = a.x; slog[j * 4 + 1] = a.y;
            slog[j * 4 + 2] = a.z; slog[j * 4 + 3] = a.w;
            ((float4*)g_alpha)[sidx[j]] = a;
        }
        __syncthreads();

        for (int j = g; j < k; j += 4) {
            float a = slog[j * 4 + hh];
            float4 xv = h4_to_f4(xh4[(size_t)snode[j] * 64 + f4]);
            acc.x += a * xv.x; acc.y += a * xv.y; acc.z += a * xv.z; acc.w += a * xv.w;
        }
    } else {
        float lmax[4] = {-1e30f, -1e30f, -1e30f, -1e30f};
        for (int j = tid; j < k; j += 256) {
            int i = g_csrE[beg + j];
            int n = nodeIdx[i];
            #pragma unroll
            for (int h = 0; h < 4; h++) {
                float z = g_ax[n * 4 + h] + aeh[h];
                z = z > 0.f ? z : 0.2f * z;
                g_alpha[i * 4 + h] = z;
                lmax[h] = fmaxf(lmax[h], z);
            }
        }
        #pragma unroll
        for (int o = 16; o; o >>= 1)
            #pragma unroll
            for (int h = 0; h < 4; h++)
                lmax[h] = fmaxf(lmax[h], __shfl_xor_sync(0xffffffffu, lmax[h], o));
        if (lane == 0)
            #pragma unroll
            for (int h = 0; h < 4; h++) wr[warp][h] = lmax[h];
        __syncthreads();
        if (tid < 4) {
            float r = wr[0][tid];
            #pragma unroll
            for (int w2 = 1; w2 < 8; w2++) r = fmaxf(r, wr[w2][tid]);
            smax[tid] = r;
        }
        __syncthreads();
        float lsum[4] = {0.f, 0.f, 0.f, 0.f};
        for (int j = tid; j < k; j += 256) {
            int i = g_csrE[beg + j];
            #pragma unroll
            for (int h = 0; h < 4; h++) {
                float ex = __expf(g_alpha[i * 4 + h] - smax[h]);
                g_alpha[i * 4 + h] = ex;
                lsum[h] += ex;
            }
        }
        #pragma unroll
        for (int o = 16; o; o >>= 1)
            #pragma unroll
            for (int h = 0; h < 4; h++) lsum[h] += __shfl_xor_sync(0xffffffffu, lsum[h], o);
        if (lane == 0)
            #pragma unroll
            for (int h = 0; h < 4; h++) wr[warp][h] = lsum[h];
        __syncthreads();
        if (tid < 4) {
            float r = wr[0][tid];
            #pragma unroll
            for (int w2 = 1; w2 < 8; w2++) r += wr[w2][tid];
            sinv[tid] = 1.f / (r + 1e-16f);
        }
        __syncthreads();
        for (int j = tid; j < k; j += 256) {
            int i = g_csrE[beg + j];
            #pragma unroll
            for (int h = 0; h < 4; h++) g_alpha[i * 4 + h] *= sinv[h];
        }
        __syncthreads();
        for (int base = 0; base < k; base += ECAP) {
            int c = min(ECAP, k - base);
            __syncthreads();
            for (int j = tid; j < c; j += 256) {
                int i = g_csrE[beg + base + j];
                snode[j] = nodeIdx[i];
                ((float4*)slog)[j] = ((const float4*)g_alpha)[i];
            }
            __syncthreads();
            for (int j = g; j < c; j += 4) {
                float a = slog[j * 4 + hh];
                float4 xv = h4_to_f4(xh4[(size_t)snode[j] * 64 + f4]);
                acc.x += a * xv.x; acc.y += a * xv.y; acc.z += a * xv.z; acc.w += a * xv.w;
            }
        }
    }

    racc[tid] = acc;
    __syncthreads();
    if (tid < 64) {
        float4 a = racc[tid], b = racc[tid + 64], c2 = racc[tid + 128], d2 = racc[tid + 192];
        float4 r;
        r.x = (a.x + b.x + c2.x + d2.x) * Binv;
        r.y = (a.y + b.y + c2.y + d2.y) * Binv;
        r.z = (a.z + b.z + c2.z + d2.z) * Binv;
        r.w = (a.w + b.w + c2.w + d2.w) * Binv;
        ((uint2*)g_eh_h)[e * 64 + tid] = f4_to_h4(r);
    }
}

__device__ __forceinline__ float eluf(float x) { return x > 0.f ? x : expm1f(x); }

// ---------------- conv1 node stage (fp16 eh gather) ----------------
__global__ __launch_bounds__(256) void node1_kernel(const int* __restrict__ hedgeIdx,
                                                    const float* __restrict__ b1) {
    int n = blockIdx.x;
    int tid = threadIdx.x;
    int beg = g_offN[n];
    int d = g_cntN[n];
    int end = beg + d;
    float Dinv = d > 0 ? 1.f / (float)d : 0.f;
    int g = tid >> 6, f4 = tid & 63, h = f4 >> 4;
    float4 acc = make_float4(0.f, 0.f, 0.f, 0.f);
    const uint2* eh4 = (const uint2*)g_eh_h;
    for (int j = beg + g; j < end; j += 4) {
        int i = g_csrN[j];
        int e = hedgeIdx[i];
        float a = g_alpha[i * 4 + h];
        float4 ev = h4_to_f4(eh4[(size_t)e * 64 + f4]);
        acc.x += a * ev.x; acc.y += a * ev.y; acc.z += a * ev.z; acc.w += a * ev.w;
    }
    __shared__ float4 racc[256];
    racc[tid] = acc;
    __syncthreads();
    if (tid < 64) {
        float4 a = racc[tid], b = racc[tid + 64], c2 = racc[tid + 128], d2 = racc[tid + 192];
        float4 bv = ((const float4*)b1)[tid];
        float4 r;
        r.x = eluf((a.x + b.x + c2.x + d2.x) * Dinv + bv.x);
        r.y = eluf((a.y + b.y + c2.y + d2.y) * Dinv + bv.y);
        r.z = eluf((a.z + b.z + c2.z + d2.z) * Dinv + bv.z);
        r.w = eluf((a.w + b.w + c2.w + d2.w) * Dinv + bv.w);
        ((float4*)g_h)[n * 64 + tid] = r;
    }
}

// ---------------- conv2 (fp16 intermediates) ----------------
__global__ __launch_bounds__(256) void edge2_kernel(const int* __restrict__ nodeIdx) {
    int e = blockIdx.x;
    int tid = threadIdx.x;
    int beg = g_offE[e];
    int k = g_cntE[e];
    int end = beg + k;
    float Binv = k > 0 ? 1.f / (float)k : 0.f;
    int g = tid >> 6, f = tid & 63;
    float acc = 0.f;
    for (int j = beg + g; j < end; j += 4) {
        int i = g_csrE[j];
        int n = nodeIdx[i];
        acc += __half2float(g_xh2_h[(size_t)n * 64 + f]);
    }
    __shared__ float racc[256];
    racc[tid] = acc;
    __syncthreads();
    if (tid < 64)
        g_eh2_h[e * 64 + tid] =
            __float2half((racc[tid] + racc[tid + 64] + racc[tid + 128] + racc[tid + 192]) * Binv);
}

__global__ __launch_bounds__(256) void node2_kernel(const int* __restrict__ hedgeIdx,
                                                    const float* __restrict__ b2,
                                                    float* __restrict__ out, int N) {
    int warp = threadIdx.x >> 5, lane = threadIdx.x & 31;
    int n = blockIdx.x * 8 + warp;
    if (n >= N) return;
    int beg = g_offN[n];
    int d = g_cntN[n];
    float Dinv = d > 0 ? 1.f / (float)d : 0.f;
    const uint32_t* eh2 = (const uint32_t*)g_eh2_h;   // half2 per uint
    float ax = 0.f, ay = 0.f;
    int j = beg, end = beg + d;
    for (; j + 1 < end; j += 2) {
        int i0 = g_csrN[j], i1 = g_csrN[j + 1];
        int e0 = hedgeIdx[i0], e1 = hedgeIdx[i1];
        uint32_t r0 = eh2[e0 * 32 + lane];
        uint32_t r1 = eh2[e1 * 32 + lane];
        float2 v0 = __half22float2(*(__half2*)&r0);
        float2 v1 = __half22float2(*(__half2*)&r1);
        ax += v0.x + v1.x; ay += v0.y + v1.y;
    }
    if (j < end) {
        int i = g_csrN[j];
        int e = hedgeIdx[i];
        uint32_t r0 = eh2[e * 32 + lane];
        float2 v = __half22float2(*(__half2*)&r0);
        ax += v.x; ay += v.y;
    }
    float2 bb = ((const float2*)b2)[lane];
    ((float2*)out)[(size_t)n * 32 + lane] = make_float2(ax * Dinv + bb.x, ay * Dinv + bb.y);
}

// ---------------- launch (R8/R12 fork structure) ----------------
extern "C" void kernel_launch(void* const* d_in, const int* in_sizes, int n_in,
                              void* d_out, int out_size) {
    const float* x    = (const float*)d_in[0];
    const int*   ei   = (const int*)d_in[1];
    const float* hat  = (const float*)d_in[2];
    const float* W1   = (const float*)d_in[3];
    const float* att1 = (const float*)d_in[4];
    const float* b1   = (const float*)d_in[5];
    const float* W2   = (const float*)d_in[6];
    const float* b2   = (const float*)d_in[7];
    float* out = (float*)d_out;

    int N   = in_sizes[0] / 128;
    int NNZ = in_sizes[1] / 2;
    int E   = in_sizes[2] / 128;
    const int* node  = ei;
    const int* hedge = ei + NNZ;

    float* p_h;
    __half *p_xh_h, *p_xh2_h;
    cudaGetSymbolAddress((void**)&p_h, g_h);
    cudaGetSymbolAddress((void**)&p_xh_h, g_xh_h);
    cudaGetSymbolAddress((void**)&p_xh2_h, g_xh2_h);

    // lazy one-time side stream + events (host objects only)
    static cudaStream_t s1 = nullptr;
    static cudaEvent_t evFork = nullptr, evJoin = nullptr;
    if (s1 == nullptr) {
        cudaStreamCreateWithFlags(&s1, cudaStreamNonBlocking);
        cudaEventCreateWithFlags(&evFork, cudaEventDisableTiming);
        cudaEventCreateWithFlags(&evJoin, cudaEventDisableTiming);
    }

    cudaEventRecord(evFork, 0);
    cudaStreamWaitEvent(s1, evFork, 0);

    // side stream (chain B): HMMA GEMM + attention logits
    hmma_gemm_kernel<<<dim3((N + 127) / 128, 2), 256, 0, s1>>>(x, W1, p_xh_h, N);
    attmat_kernel<<<1, 512, 0, s1>>>(W1, att1);
    axae_kernel<<<(N + E + 255) / 256, 256, 0, s1>>>(x, hat, N, E);
    cudaEventRecord(evJoin, s1);

    // main stream (chain A): CSR build
    zero_counts_kernel<<<128, 256>>>(N, E);
    count_kernel<<<480, 256>>>(node, hedge, NNZ);
    alloc_kernel<<<64, 256>>>(N, E);
    scatter_kernel<<<480, 256>>>(node, hedge, NNZ);

    // join
    cudaStreamWaitEvent(0, evJoin, 0);

    // conv1
    edge1_kernel<<<E, 256>>>(node);
    node1_kernel<<<N, 256>>>(hedge, b1);

    // conv2
    sgemm_h_out_kernel<128, 64, 16, 8, 4><<<dim3((N + 127) / 128, 1), 256>>>(p_h, W2, p_xh2_h, N, 64, 256);
    edge2_kernel<<<E, 256>>>(node);
    node2_kernel<<<(N + 7) / 8, 256>>>(hedge, b2, out, N);
}

// round 14
// speedup vs baseline: 1.6280x; 1.1097x over previous
#include <cuda_runtime.h>
#include <cuda_fp16.h>
#include <math.h>
#include <cstdint>

#define MAXN   50000
#define MAXE   10000
#define MAXNNZ 600000

// ---------------- scratch (static __device__, no allocations) ----------------
__device__ __half g_xh_h[MAXN * 256];  // x @ W1 (fp16, consumed by edge1)
__device__ __half g_eh_h[MAXE * 256];  // propagate-1 out (fp16, consumed by node1)
__device__ __half g_h_h[MAXN * 256];   // elu(conv1 out) (fp16, consumed by conv2 GEMM)
__device__ __half g_xh2_h[MAXN * 64];  // h @ W2 (fp16, consumed by edge2)
__device__ __half g_eh2_h[MAXE * 64];  // conv2 edge out (fp16, consumed by node2)
__device__ float g_ax[MAXN * 4];
__device__ float g_ae[MAXE * 4];
__device__ float g_A1[128 * 4];
__device__ float g_A2[128 * 4];
__device__ float g_alpha[MAXNNZ * 4];
__device__ int g_cntN[MAXN], g_cntE[MAXE];
__device__ int g_curN[MAXN], g_curE[MAXE];
__device__ int g_offN[MAXN], g_offE[MAXE];
__device__ int g_csrN[MAXNNZ], g_csrE[MAXNNZ];
__device__ int g_totN, g_totE;

__device__ __forceinline__ float4 h4_to_f4(uint2 raw) {
    __half2 h0 = *(__half2*)&raw.x;
    __half2 h1 = *(__half2*)&raw.y;
    float2 a = __half22float2(h0), b = __half22float2(h1);
    return make_float4(a.x, a.y, b.x, b.y);
}
__device__ __forceinline__ uint2 f4_to_h4(float4 v) {
    __half2 h0 = __floats2half2_rn(v.x, v.y);
    __half2 h1 = __floats2half2_rn(v.z, v.w);
    uint2 r;
    r.x = *(uint32_t*)&h0;
    r.y = *(uint32_t*)&h1;
    return r;
}

__device__ __forceinline__ void mma_f16(float* c, const uint32_t* a, const uint32_t* b) {
    asm volatile(
        "mma.sync.aligned.m16n8k16.row.col.f32.f16.f16.f32 "
        "{%0,%1,%2,%3}, {%4,%5,%6,%7}, {%8,%9}, {%0,%1,%2,%3};"
        : "+f"(c[0]), "+f"(c[1]), "+f"(c[2]), "+f"(c[3])
        : "r"(a[0]), "r"(a[1]), "r"(a[2]), "r"(a[3]), "r"(b[0]), "r"(b[1]));
}

// ---------------- HMMA GEMM 1: xh = x @ W1 (fp32 in, fp16 out) ----------------
// BM=BN=128, BK=32, 8 warps (2x4), warp tile 64x32, MT=NT=4.
__global__ __launch_bounds__(256) void hmma_gemm_kernel(const float* __restrict__ A,
                                                        const float* __restrict__ B,
                                                        __half* __restrict__ C, int M) {
    const int K = 128, NG = 256;
    __shared__ uint32_t AsU[128 * 18];
    __shared__ uint32_t BsU[128 * 18];
    __half* Bs_h = (__half*)BsU;
    int tid = threadIdx.x, lane = tid & 31, wid = tid >> 5;
    int gid = lane >> 2, tig = lane & 3;
    int warpM = wid >> 2, warpN = wid & 3;
    int rowBase = blockIdx.x * 128, colBase = blockIdx.y * 128;
    float acc[4][4][4] = {};

    for (int kt = 0; kt < K; kt += 32) {
        #pragma unroll
        for (int u = 0; u < 4; u++) {
            int l = tid + u * 256;
            int r = l >> 3, c4 = l & 7;
            int gr = rowBase + r;
            float4 v = make_float4(0.f, 0.f, 0.f, 0.f);
            if (gr < M) v = *(const float4*)&A[(size_t)gr * K + kt + c4 * 4];
            __half2 h01 = __floats2half2_rn(v.x, v.y);
            __half2 h23 = __floats2half2_rn(v.z, v.w);
            AsU[r * 18 + c4 * 2 + 0] = *(uint32_t*)&h01;
            AsU[r * 18 + c4 * 2 + 1] = *(uint32_t*)&h23;
        }
        #pragma unroll
        for (int u = 0; u < 4; u++) {
            int l = tid + u * 256;
            int k = l >> 5, n4 = l & 31;
            float4 v = *(const float4*)&B[(size_t)(kt + k) * NG + colBase + n4 * 4];
            Bs_h[(n4 * 4 + 0) * 36 + k] = __float2half(v.x);
            Bs_h[(n4 * 4 + 1) * 36 + k] = __float2half(v.y);
            Bs_h[(n4 * 4 + 2) * 36 + k] = __float2half(v.z);
            Bs_h[(n4 * 4 + 3) * 36 + k] = __float2half(v.w);
        }
        __syncthreads();
        #pragma unroll
        for (int s = 0; s < 2; s++) {
            uint32_t af[4][4], bf[4][2];
            #pragma unroll
            for (int mt = 0; mt < 4; mt++) {
                int r = warpM * 64 + mt * 16 + gid;
                af[mt][0] = AsU[r * 18 + s * 8 + tig];
                af[mt][1] = AsU[(r + 8) * 18 + s * 8 + tig];
                af[mt][2] = AsU[r * 18 + s * 8 + tig + 4];
                af[mt][3] = AsU[(r + 8) * 18 + s * 8 + tig + 4];
            }
            #pragma unroll
            for (int nt = 0; nt < 4; nt++) {
                int n = warpN * 32 + nt * 8 + gid;
                bf[nt][0] = BsU[n * 18 + s * 8 + tig];
                bf[nt][1] = BsU[n * 18 + s * 8 + tig + 4];
            }
            #pragma unroll
            for (int mt = 0; mt < 4; mt++)
                #pragma unroll
                for (int nt = 0; nt < 4; nt++) mma_f16(acc[mt][nt], af[mt], bf[nt]);
        }
        __syncthreads();
    }

    #pragma unroll
    for (int mt = 0; mt < 4; mt++) {
        int r0 = rowBase + warpM * 64 + mt * 16 + gid;
        #pragma unroll
        for (int nt = 0; nt < 4; nt++) {
            int c = colBase + warpN * 32 + nt * 8 + tig * 2;
            if (r0 < M) {
                __half2 h = __floats2half2_rn(acc[mt][nt][0], acc[mt][nt][1]);
                *(uint32_t*)&C[(size_t)r0 * NG + c] = *(uint32_t*)&h;
            }
            if (r0 + 8 < M) {
                __half2 h = __floats2half2_rn(acc[mt][nt][2], acc[mt][nt][3]);
                *(uint32_t*)&C[(size_t)(r0 + 8) * NG + c] = *(uint32_t*)&h;
            }
        }
    }
}

// ---------------- HMMA GEMM 2: xh2 = h @ W2 (fp16 A in, fp16 out) ----------------
// BM=128, BN=64, BK=32, K=256; 8 warps (4x2), warp tile 32x32, MT=2, NT=4.
__global__ __launch_bounds__(256) void hmma_gemm2_kernel(const __half* __restrict__ A,
                                                         const float* __restrict__ B,
                                                         __half* __restrict__ C, int M) {
    const int K = 256, NG = 64;
    __shared__ uint32_t AsU[128 * 18];
    __shared__ uint32_t BsU[64 * 18];
    __half* Bs_h = (__half*)BsU;
    int tid = threadIdx.x, lane = tid & 31, wid = tid >> 5;
    int gid = lane >> 2, tig = lane & 3;
    int warpM = wid >> 1, warpN = wid & 1;
    int rowBase = blockIdx.x * 128;
    float acc[2][4][4] = {};

    for (int kt = 0; kt < K; kt += 32) {
        // A tile: 128 rows x 32 halves, direct fp16 copy (uint2 = 4 halves)
        #pragma unroll
        for (int u = 0; u < 4; u++) {
            int l = tid + u * 256;
            int r = l >> 3, c4 = l & 7;
            int gr = rowBase + r;
            uint2 v = make_uint2(0u, 0u);
            if (gr < M) v = *(const uint2*)&A[(size_t)gr * K + kt + c4 * 4];
            AsU[r * 18 + c4 * 2 + 0] = v.x;
            AsU[r * 18 + c4 * 2 + 1] = v.y;
        }
        // B tile: 32 k x 64 n fp32 -> half, transposed to Bs[n][k]
        #pragma unroll
        for (int u = 0; u < 2; u++) {
            int l = tid + u * 256;
            int k = l >> 4, n4 = l & 15;
            float4 v = *(const float4*)&B[(size_t)(kt + k) * NG + n4 * 4];
            Bs_h[(n4 * 4 + 0) * 36 + k] = __float2half(v.x);
            Bs_h[(n4 * 4 + 1) * 36 + k] = __float2half(v.y);
            Bs_h[(n4 * 4 + 2) * 36 + k] = __float2half(v.z);
            Bs_h[(n4 * 4 + 3) * 36 + k] = __float2half(v.w);
        }
        __syncthreads();
        #pragma unroll
        for (int s = 0; s < 2; s++) {
            uint32_t af[2][4], bf[4][2];
            #pragma unroll
            for (int mt = 0; mt < 2; mt++) {
                int r = warpM * 32 + mt * 16 + gid;
                af[mt][0] = AsU[r * 18 + s * 8 + tig];
                af[mt][1] = AsU[(r + 8) * 18 + s * 8 + tig];
                af[mt][2] = AsU[r * 18 + s * 8 + tig + 4];
                af[mt][3] = AsU[(r + 8) * 18 + s * 8 + tig + 4];
            }
            #pragma unroll
            for (int nt = 0; nt < 4; nt++) {
                int n = warpN * 32 + nt * 8 + gid;
                bf[nt][0] = BsU[n * 18 + s * 8 + tig];
                bf[nt][1] = BsU[n * 18 + s * 8 + tig + 4];
            }
            #pragma unroll
            for (int mt = 0; mt < 2; mt++)
                #pragma unroll
                for (int nt = 0; nt < 4; nt++) mma_f16(acc[mt][nt], af[mt], bf[nt]);
        }
        __syncthreads();
    }

    #pragma unroll
    for (int mt = 0; mt < 2; mt++) {
        int r0 = rowBase + warpM * 32 + mt * 16 + gid;
        #pragma unroll
        for (int nt = 0; nt < 4; nt++) {
            int c = warpN * 32 + nt * 8 + tig * 2;
            if (r0 < M) {
                __half2 h = __floats2half2_rn(acc[mt][nt][0], acc[mt][nt][1]);
                *(uint32_t*)&C[(size_t)r0 * NG + c] = *(uint32_t*)&h;
            }
            if (r0 + 8 < M) {
                __half2 h = __floats2half2_rn(acc[mt][nt][2], acc[mt][nt][3]);
                *(uint32_t*)&C[(size_t)(r0 + 8) * NG + c] = *(uint32_t*)&h;
            }
        }
    }
}

// ---------------- CSR construction ----------------
__global__ void zero_counts_kernel(int N, int E) {
    int i = blockIdx.x * blockDim.x + threadIdx.x;
    int s = gridDim.x * blockDim.x;
    if (i == 0) { g_totN = 0; g_totE = 0; }
    for (int j = i; j < N; j += s) { g_cntN[j] = 0; g_curN[j] = 0; }
    for (int j = i; j < E; j += s) { g_cntE[j] = 0; g_curE[j] = 0; }
}

__global__ void count_kernel(const int* __restrict__ node, const int* __restrict__ hedge, int nnz) {
    int t = blockIdx.x * blockDim.x + threadIdx.x;
    int stride4 = gridDim.x * blockDim.x * 4;
    for (int j0 = t * 4; j0 < nnz; j0 += stride4) {
        if (j0 + 3 < nnz) {
            int4 n4 = *(const int4*)&node[j0];
            int4 h4 = *(const int4*)&hedge[j0];
            atomicAdd(&g_cntN[n4.x], 1); atomicAdd(&g_cntN[n4.y], 1);
            atomicAdd(&g_cntN[n4.z], 1); atomicAdd(&g_cntN[n4.w], 1);
            atomicAdd(&g_cntE[h4.x], 1); atomicAdd(&g_cntE[h4.y], 1);
            atomicAdd(&g_cntE[h4.z], 1); atomicAdd(&g_cntE[h4.w], 1);
        } else {
            for (int j = j0; j < nnz; j++) {
                atomicAdd(&g_cntN[node[j]], 1);
                atomicAdd(&g_cntE[hedge[j]], 1);
            }
        }
    }
}

__device__ __forceinline__ void alloc_ranges(const int* __restrict__ cnt, int* __restrict__ off,
                                             int* total, int n, int gwarp, int nwarps, int lane) {
    for (int j0 = gwarp * 32; j0 < n; j0 += nwarps * 32) {
        int j = j0 + lane;
        int c = (j < n) ? cnt[j] : 0;
        int x = c;
        #pragma unroll
        for (int o = 1; o < 32; o <<= 1) {
            int y = __shfl_up_sync(0xffffffffu, x, o);
            if (lane >= o) x += y;
        }
        int wtot = __shfl_sync(0xffffffffu, x, 31);
        int base = 0;
        if (lane == 0) base = atomicAdd(total, wtot);
        base = __shfl_sync(0xffffffffu, base, 0);
        if (j < n) off[j] = base + x - c;
    }
}

__global__ void alloc_kernel(int N, int E) {
    int t = blockIdx.x * blockDim.x + threadIdx.x;
    int gwarp = t >> 5, lane = t & 31;
    int nwarps = (gridDim.x * blockDim.x) >> 5;
    alloc_ranges(g_cntN, g_offN, &g_totN, N, gwarp, nwarps, lane);
    alloc_ranges(g_cntE, g_offE, &g_totE, E, gwarp, nwarps, lane);
}

__global__ void scatter_kernel(const int* __restrict__ node, const int* __restrict__ hedge, int nnz) {
    int t = blockIdx.x * blockDim.x + threadIdx.x;
    int stride4 = gridDim.x * blockDim.x * 4;
    for (int j0 = t * 4; j0 < nnz; j0 += stride4) {
        if (j0 + 3 < nnz) {
            int4 n4 = *(const int4*)&node[j0];
            int4 h4 = *(const int4*)&hedge[j0];
            g_csrN[g_offN[n4.x] + atomicAdd(&g_curN[n4.x], 1)] = j0 + 0;
            g_csrN[g_offN[n4.y] + atomicAdd(&g_curN[n4.y], 1)] = j0 + 1;
            g_csrN[g_offN[n4.z] + atomicAdd(&g_curN[n4.z], 1)] = j0 + 2;
            g_csrN[g_offN[n4.w] + atomicAdd(&g_curN[n4.w], 1)] = j0 + 3;
            g_csrE[g_offE[h4.x] + atomicAdd(&g_curE[h4.x], 1)] = j0 + 0;
            g_csrE[g_offE[h4.y] + atomicAdd(&g_curE[h4.y], 1)] = j0 + 1;
            g_csrE[g_offE[h4.z] + atomicAdd(&g_curE[h4.z], 1)] = j0 + 2;
            g_csrE[g_offE[h4.w] + atomicAdd(&g_curE[h4.w], 1)] = j0 + 3;
        } else {
            for (int j = j0; j < nnz; j++) {
                int n = node[j], h = hedge[j];
                g_csrN[g_offN[n] + atomicAdd(&g_curN[n], 1)] = j;
                g_csrE[g_offE[h] + atomicAdd(&g_curE[h], 1)] = j;
            }
        }
    }
}

// ---------------- fold att into W1 ----------------
__global__ void attmat_kernel(const float* __restrict__ W1, const float* __restrict__ att) {
    int t = threadIdx.x;           // 512 threads
    int k = t >> 2, h = t & 3;
    const float* wrow = &W1[k * 256 + h * 64];
    const float* a1 = &att[h * 128];
    const float* a2 = &att[h * 128 + 64];
    float s1 = 0.f, s2 = 0.f;
    #pragma unroll
    for (int f = 0; f < 64; f++) {
        float w = wrow[f];
        s1 += w * a1[f];
        s2 += w * a2[f];
    }
    g_A1[k * 4 + h] = s1;
    g_A2[k * 4 + h] = s2;
}

// ---------------- attention logits ----------------
__global__ __launch_bounds__(256) void axae_kernel(const float* __restrict__ x,
                                                   const float* __restrict__ hat, int N, int E) {
    __shared__ float sA1[128 * 4], sA2[128 * 4];
    int tid = threadIdx.x;
    for (int i = tid; i < 512; i += 256) { sA1[i] = g_A1[i]; sA2[i] = g_A2[i]; }
    __syncthreads();
    int r = blockIdx.x * 256 + tid;
    if (r >= N + E) return;
    bool isNode = r < N;
    const float4* row = (const float4*)(isNode ? &x[(size_t)r * 128] : &hat[(size_t)(r - N) * 128]);
    const float* Am = isNode ? sA1 : sA2;
    float acc0 = 0.f, acc1 = 0.f, acc2 = 0.f, acc3 = 0.f;
    #pragma unroll
    for (int k4 = 0; k4 < 32; k4++) {
        float4 v = row[k4];
        const float* a = &Am[k4 * 16];
        acc0 += v.x * a[0];  acc1 += v.x * a[1];  acc2 += v.x * a[2];  acc3 += v.x * a[3];
        acc0 += v.y * a[4];  acc1 += v.y * a[5];  acc2 += v.y * a[6];  acc3 += v.y * a[7];
        acc0 += v.z * a[8];  acc1 += v.z * a[9];  acc2 += v.z * a[10]; acc3 += v.z * a[11];
        acc0 += v.w * a[12]; acc1 += v.w * a[13]; acc2 += v.w * a[14]; acc3 += v.w * a[15];
    }
    float* dst = isNode ? &g_ax[r * 4] : &g_ae[(r - N) * 4];
    dst[0] = acc0; dst[1] = acc1; dst[2] = acc2; dst[3] = acc3;
}

// ---------------- conv1 edge stage: segment softmax + propagate 1 (fp16 gather) ----------------
#define ECAP 1024
__global__ __launch_bounds__(256) void edge1_kernel(const int* __restrict__ nodeIdx) {
    int e = blockIdx.x;
    int tid = threadIdx.x;
    int lane = tid & 31, warp = tid >> 5;
    int beg = g_offE[e];
    int k = g_cntE[e];
    float aeh[4];
    #pragma unroll
    for (int h = 0; h < 4; h++) aeh[h] = g_ae[e * 4 + h];

    __shared__ int snode[ECAP];
    __shared__ int sidx[ECAP];
    __shared__ float slog[ECAP * 4];
    __shared__ float4 racc[256];
    __shared__ float wr[8][4];
    __shared__ float smax[4], sinv[4];

    int g = tid >> 6, f4 = tid & 63, hh = f4 >> 4;
    float Binv = k > 0 ? 1.f / (float)k : 0.f;
    float4 acc = make_float4(0.f, 0.f, 0.f, 0.f);
    const uint2* xh4 = (const uint2*)g_xh_h;

    if (k <= ECAP) {
        float lmax[4] = {-1e30f, -1e30f, -1e30f, -1e30f};
        for (int j = tid; j < k; j += 256) {
            int i = g_csrE[beg + j];
            int n = nodeIdx[i];
            sidx[j] = i;
            snode[j] = n;
            #pragma unroll
            for (int h = 0; h < 4; h++) {
                float z = g_ax[n * 4 + h] + aeh[h];
                z = z > 0.f ? z : 0.2f * z;
                slog[j * 4 + h] = z;
                lmax[h] = fmaxf(lmax[h], z);
            }
        }
        #pragma unroll
        for (int o = 16; o; o >>= 1)
            #pragma unroll
            for (int h = 0; h < 4; h++)
                lmax[h] = fmaxf(lmax[h], __shfl_xor_sync(0xffffffffu, lmax[h], o));
        if (lane == 0)
            #pragma unroll
            for (int h = 0; h < 4; h++) wr[warp][h] = lmax[h];
        __syncthreads();
        if (tid < 4) {
            float r = wr[0][tid];
            #pragma unroll
            for (int w2 = 1; w2 < 8; w2++) r = fmaxf(r, wr[w2][tid]);
            smax[tid] = r;
        }
        __syncthreads();

        float lsum[4] = {0.f, 0.f, 0.f, 0.f};
        for (int j = tid; j < k; j += 256) {
            #pragma unroll
            for (int h = 0; h < 4; h++) {
                float ex = __expf(slog[j * 4 + h] - smax[h]);
                slog[j * 4 + h] = ex;
                lsum[h] += ex;
            }
        }
        #pragma unroll
        for (int o = 16; o; o >>= 1)
            #pragma unroll
            for (int h = 0; h < 4; h++) lsum[h] += __shfl_xor_sync(0xffffffffu, lsum[h], o);
        if (lane == 0)
            #pragma unroll
            for (int h = 0; h < 4; h++) wr[warp][h] = lsum[h];
        __syncthreads();
        if (tid < 4) {
            float r = wr[0][tid];
            #pragma unroll
            for (int w2 = 1; w2 < 8; w2++) r += wr[w2][tid];
            sinv[tid] = 1.f / (r + 1e-16f);
        }
        __syncthreads();

        for (int j = tid; j < k; j += 256) {
            float4 a;
            a.x = slog[j * 4 + 0] * sinv[0];
            a.y = slog[j * 4 + 1] * sinv[1];
            a.z = slog[j * 4 + 2] * sinv[2];
            a.w = slog[j * 4 + 3] * sinv[3];
            slog[j * 4 + 0] = a.x; slog[j * 4 + 1] = a.y;
            slog[j * 4 + 2] = a.z; slog[j * 4 + 3] = a.w;
            ((float4*)g_alpha)[sidx[j]] = a;
        }
        __syncthreads();

        for (int j = g; j < k; j += 4) {
            float a = slog[j * 4 + hh];
            float4 xv = h4_to_f4(xh4[(size_t)snode[j] * 64 + f4]);
            acc.x += a * xv.x; acc.y += a * xv.y; acc.z += a * xv.z; acc.w += a * xv.w;
        }
    } else {
        float lmax[4] = {-1e30f, -1e30f, -1e30f, -1e30f};
        for (int j = tid; j < k; j += 256) {
            int i = g_csrE[beg + j];
            int n = nodeIdx[i];
            #pragma unroll
            for (int h = 0; h < 4; h++) {
                float z = g_ax[n * 4 + h] + aeh[h];
                z = z > 0.f ? z : 0.2f * z;
                g_alpha[i * 4 + h] = z;
                lmax[h] = fmaxf(lmax[h], z);
            }
        }
        #pragma unroll
        for (int o = 16; o; o >>= 1)
            #pragma unroll
            for (int h = 0; h < 4; h++)
                lmax[h] = fmaxf(lmax[h], __shfl_xor_sync(0xffffffffu, lmax[h], o));
        if (lane == 0)
            #pragma unroll
            for (int h = 0; h < 4; h++) wr[warp][h] = lmax[h];
        __syncthreads();
        if (tid < 4) {
            float r = wr[0][tid];
            #pragma unroll
            for (int w2 = 1; w2 < 8; w2++) r = fmaxf(r, wr[w2][tid]);
            smax[tid] = r;
        }
        __syncthreads();
        float lsum[4] = {0.f, 0.f, 0.f, 0.f};
        for (int j = tid; j < k; j += 256) {
            int i = g_csrE[beg + j];
            #pragma unroll
            for (int h = 0; h < 4; h++) {
                float ex = __expf(g_alpha[i * 4 + h] - smax[h]);
                g_alpha[i * 4 + h] = ex;
                lsum[h] += ex;
            }
        }
        #pragma unroll
        for (int o = 16; o; o >>= 1)
            #pragma unroll
            for (int h = 0; h < 4; h++) lsum[h] += __shfl_xor_sync(0xffffffffu, lsum[h], o);
        if (lane == 0)
            #pragma unroll
            for (int h = 0; h < 4; h++) wr[warp][h] = lsum[h];
        __syncthreads();
        if (tid < 4) {
            float r = wr[0][tid];
            #pragma unroll
            for (int w2 = 1; w2 < 8; w2++) r += wr[w2][tid];
            sinv[tid] = 1.f / (r + 1e-16f);
        }
        __syncthreads();
        for (int j = tid; j < k; j += 256) {
            int i = g_csrE[beg + j];
            #pragma unroll
            for (int h = 0; h < 4; h++) g_alpha[i * 4 + h] *= sinv[h];
        }
        __syncthreads();
        for (int base = 0; base < k; base += ECAP) {
            int c = min(ECAP, k - base);
            __syncthreads();
            for (int j = tid; j < c; j += 256) {
                int i = g_csrE[beg + base + j];
                snode[j] = nodeIdx[i];
                ((float4*)slog)[j] = ((const float4*)g_alpha)[i];
            }
            __syncthreads();
            for (int j = g; j < c; j += 4) {
                float a = slog[j * 4 + hh];
                float4 xv = h4_to_f4(xh4[(size_t)snode[j] * 64 + f4]);
                acc.x += a * xv.x; acc.y += a * xv.y; acc.z += a * xv.z; acc.w += a * xv.w;
            }
        }
    }

    racc[tid] = acc;
    __syncthreads();
    if (tid < 64) {
        float4 a = racc[tid], b = racc[tid + 64], c2 = racc[tid + 128], d2 = racc[tid + 192];
        float4 r;
        r.x = (a.x + b.x + c2.x + d2.x) * Binv;
        r.y = (a.y + b.y + c2.y + d2.y) * Binv;
        r.z = (a.z + b.z + c2.z + d2.z) * Binv;
        r.w = (a.w + b.w + c2.w + d2.w) * Binv;
        ((uint2*)g_eh_h)[e * 64 + tid] = f4_to_h4(r);
    }
}

__device__ __forceinline__ float eluf(float x) { return x > 0.f ? x : expm1f(x); }

// ---------------- conv1 node stage (fp16 eh gather, fp16 h out) ----------------
__global__ __launch_bounds__(256) void node1_kernel(const int* __restrict__ hedgeIdx,
                                                    const float* __restrict__ b1) {
    int n = blockIdx.x;
    int tid = threadIdx.x;
    int beg = g_offN[n];
    int d = g_cntN[n];
    int end = beg + d;
    float Dinv = d > 0 ? 1.f / (float)d : 0.f;
    int g = tid >> 6, f4 = tid & 63, h = f4 >> 4;
    float4 acc = make_float4(0.f, 0.f, 0.f, 0.f);
    const uint2* eh4 = (const uint2*)g_eh_h;
    for (int j = beg + g; j < end; j += 4) {
        int i = g_csrN[j];
        int e = hedgeIdx[i];
        float a = g_alpha[i * 4 + h];
        float4 ev = h4_to_f4(eh4[(size_t)e * 64 + f4]);
        acc.x += a * ev.x; acc.y += a * ev.y; acc.z += a * ev.z; acc.w += a * ev.w;
    }
    __shared__ float4 racc[256];
    racc[tid] = acc;
    __syncthreads();
    if (tid < 64) {
        float4 a = racc[tid], b = racc[tid + 64], c2 = racc[tid + 128], d2 = racc[tid + 192];
        float4 bv = ((const float4*)b1)[tid];
        float4 r;
        r.x = eluf((a.x + b.x + c2.x + d2.x) * Dinv + bv.x);
        r.y = eluf((a.y + b.y + c2.y + d2.y) * Dinv + bv.y);
        r.z = eluf((a.z + b.z + c2.z + d2.z) * Dinv + bv.z);
        r.w = eluf((a.w + b.w + c2.w + d2.w) * Dinv + bv.w);
        ((uint2*)g_h_h)[(size_t)n * 64 + tid] = f4_to_h4(r);
    }
}

// ---------------- conv2 (fp16 intermediates) ----------------
__global__ __launch_bounds__(256) void edge2_kernel(const int* __restrict__ nodeIdx) {
    int e = blockIdx.x;
    int tid = threadIdx.x;
    int beg = g_offE[e];
    int k = g_cntE[e];
    int end = beg + k;
    float Binv = k > 0 ? 1.f / (float)k : 0.f;
    int g = tid >> 6, f = tid & 63;
    float acc = 0.f;
    for (int j = beg + g; j < end; j += 4) {
        int i = g_csrE[j];
        int n = nodeIdx[i];
        acc += __half2float(g_xh2_h[(size_t)n * 64 + f]);
    }
    __shared__ float racc[256];
    racc[tid] = acc;
    __syncthreads();
    if (tid < 64)
        g_eh2_h[e * 64 + tid] =
            __float2half((racc[tid] + racc[tid + 64] + racc[tid + 128] + racc[tid + 192]) * Binv);
}

__global__ __launch_bounds__(256) void node2_kernel(const int* __restrict__ hedgeIdx,
                                                    const float* __restrict__ b2,
                                                    float* __restrict__ out, int N) {
    int warp = threadIdx.x >> 5, lane = threadIdx.x & 31;
    int n = blockIdx.x * 8 + warp;
    if (n >= N) return;
    int beg = g_offN[n];
    int d = g_cntN[n];
    float Dinv = d > 0 ? 1.f / (float)d : 0.f;
    const uint32_t* eh2 = (const uint32_t*)g_eh2_h;
    float ax = 0.f, ay = 0.f;
    int j = beg, end = beg + d;
    for (; j + 1 < end; j += 2) {
        int i0 = g_csrN[j], i1 = g_csrN[j + 1];
        int e0 = hedgeIdx[i0], e1 = hedgeIdx[i1];
        uint32_t r0 = eh2[e0 * 32 + lane];
        uint32_t r1 = eh2[e1 * 32 + lane];
        float2 v0 = __half22float2(*(__half2*)&r0);
        float2 v1 = __half22float2(*(__half2*)&r1);
        ax += v0.x + v1.x; ay += v0.y + v1.y;
    }
    if (j < end) {
        int i = g_csrN[j];
        int e = hedgeIdx[i];
        uint32_t r0 = eh2[e * 32 + lane];
        float2 v = __half22float2(*(__half2*)&r0);
        ax += v.x; ay += v.y;
    }
    float2 bb = ((const float2*)b2)[lane];
    ((float2*)out)[(size_t)n * 32 + lane] = make_float2(ax * Dinv + bb.x, ay * Dinv + bb.y);
}

// ---------------- launch (R8/R12 fork structure) ----------------
extern "C" void kernel_launch(void* const* d_in, const int* in_sizes, int n_in,
                              void* d_out, int out_size) {
    const float* x    = (const float*)d_in[0];
    const int*   ei   = (const int*)d_in[1];
    const float* hat  = (const float*)d_in[2];
    const float* W1   = (const float*)d_in[3];
    const float* att1 = (const float*)d_in[4];
    const float* b1   = (const float*)d_in[5];
    const float* W2   = (const float*)d_in[6];
    const float* b2   = (const float*)d_in[7];
    float* out = (float*)d_out;

    int N   = in_sizes[0] / 128;
    int NNZ = in_sizes[1] / 2;
    int E   = in_sizes[2] / 128;
    const int* node  = ei;
    const int* hedge = ei + NNZ;

    __half *p_xh_h, *p_h_h, *p_xh2_h;
    cudaGetSymbolAddress((void**)&p_xh_h, g_xh_h);
    cudaGetSymbolAddress((void**)&p_h_h, g_h_h);
    cudaGetSymbolAddress((void**)&p_xh2_h, g_xh2_h);

    // lazy one-time side stream + events (host objects only)
    static cudaStream_t s1 = nullptr;
    static cudaEvent_t evFork = nullptr, evJoin = nullptr;
    if (s1 == nullptr) {
        cudaStreamCreateWithFlags(&s1, cudaStreamNonBlocking);
        cudaEventCreateWithFlags(&evFork, cudaEventDisableTiming);
        cudaEventCreateWithFlags(&evJoin, cudaEventDisableTiming);
    }

    cudaEventRecord(evFork, 0);
    cudaStreamWaitEvent(s1, evFork, 0);

    // side stream (chain B): HMMA GEMM + attention logits
    hmma_gemm_kernel<<<dim3((N + 127) / 128, 2), 256, 0, s1>>>(x, W1, p_xh_h, N);
    attmat_kernel<<<1, 512, 0, s1>>>(W1, att1);
    axae_kernel<<<(N + E + 255) / 256, 256, 0, s1>>>(x, hat, N, E);
    cudaEventRecord(evJoin, s1);

    // main stream (chain A): CSR build
    zero_counts_kernel<<<128, 256>>>(N, E);
    count_kernel<<<480, 256>>>(node, hedge, NNZ);
    alloc_kernel<<<64, 256>>>(N, E);
    scatter_kernel<<<480, 256>>>(node, hedge, NNZ);

    // join
    cudaStreamWaitEvent(0, evJoin, 0);

    // conv1
    edge1_kernel<<<E, 256>>>(node);
    node1_kernel<<<N, 256>>>(hedge, b1);

    // conv2 (HMMA, fp16 in/out)
    hmma_gemm2_kernel<<<(N + 127) / 128, 256>>>(p_h_h, W2, p_xh2_h, N);
    edge2_kernel<<<E, 256>>>(node);
    node2_kernel<<<(N + 7) / 8, 256>>>(hedge, b2, out, N);
}